// round 8
// baseline (speedup 1.0000x reference)
#include <cuda_runtime.h>

#define HH 1024
#define WW 1024
#define NPIX (HH * WW)
#define NB 8
#define NBLK 512   // stats slots per plane: 64 tiles x 8 warp-strips

#define P_ 0.19487471f   // sqrt(0.03797616)
#define Q_ 0.23021729f   // sqrt(0.053); outer([p,q,p],[p,q,p]) == reference 3x3
#define WFULL 0xffffffffu

__device__ float    g_buf[2][2][NB * NPIX];
__device__ float    g_part[NB][5][NBLK];
__device__ unsigned g_barcnt;
__device__ volatile unsigned g_sense;

__inline__ __device__ float warpSumF(float v) {
#pragma unroll
    for (int o = 16; o; o >>= 1) v += __shfl_down_sync(WFULL, v, o);
    return v;
}
__inline__ __device__ double warpSumD(double v) {
#pragma unroll
    for (int o = 16; o; o >>= 1) v += __shfl_down_sync(WFULL, v, o);
    return v;
}

// ---- row load: thread's float4 of row gy + edge scalars for lanes 0/31 ----
template <int NCH>
__device__ __forceinline__ float4 load_row(const float* __restrict__ s, int gy,
                                           int x0, int lane, float& e0, float& e1) {
    e0 = 0.f; e1 = 0.f;
    if ((unsigned)gy >= HH) return make_float4(0.f, 0.f, 0.f, 0.f);
    const float* r = s + (size_t)gy * WW;
    const float* q = r + x0 + lane * 4;
    float4 a = *(const float4*)q;
    if (NCH == 3) {
        float4 b = *(const float4*)(q + NPIX);
        float4 c = *(const float4*)(q + 2 * NPIX);
        a.x += b.x + c.x; a.y += b.y + c.y; a.z += b.z + c.z; a.w += b.w + c.w;
    }
    if (lane == 0) {
        if (x0 > 0) {
            e0 = r[x0 - 2]; e1 = r[x0 - 1];
            if (NCH == 3) {
                e0 += r[x0 - 2 + NPIX] + r[x0 - 2 + 2 * NPIX];
                e1 += r[x0 - 1 + NPIX] + r[x0 - 1 + 2 * NPIX];
            }
        }
    } else if (lane == 31) {
        if (x0 < WW - 128) {
            e0 = r[x0 + 128]; e1 = r[x0 + 129];
            if (NCH == 3) {
                e0 += r[x0 + 128 + NPIX] + r[x0 + 128 + 2 * NPIX];
                e1 += r[x0 + 129 + NPIX] + r[x0 + 129 + 2 * NPIX];
            }
        }
    }
    return a;
}

// ---- double-conv register pipeline (per warp, shuffles for horizontal) ----
struct DPipe {
    float4 h1a, h1b, h1c, h2a, h2b, h2c;
    float ea, eb, ec;   // lane0: h1 at col x0-1 ; lane31: h1 at col x0+128
};

// Push input row j; returns out row j-2 (valid once 4 rows pushed).
__device__ __forceinline__ float4 dstep(DPipe& pp, float4 x, float e0, float e1,
                                        int lane, int gv, bool xlo, bool xhi) {
    float xl = __shfl_up_sync(WFULL, x.w, 1);   if (lane == 0)  xl = e1;
    float xr = __shfl_down_sync(WFULL, x.x, 1); if (lane == 31) xr = e0;
    float4 h;
    h.x = P_ * (xl + x.y) + Q_ * x.x;
    h.y = P_ * (x.x + x.z) + Q_ * x.y;
    h.z = P_ * (x.y + x.w) + Q_ * x.z;
    h.w = P_ * (x.z + xr) + Q_ * x.w;
    // edge h1: lane0 -> col -1 (x[-2]=e0, x[-1]=e1, x[0]=a.x); lane31 -> col 128
    float sA = (lane == 0) ? e0 : x.w;
    float sB = (lane == 0) ? x.x : e1;
    float sC = (lane == 0) ? e1 : e0;
    float he = P_ * (sA + sB) + Q_ * sC;
    pp.h1a = pp.h1b; pp.h1b = pp.h1c; pp.h1c = h;
    pp.ea = pp.eb;   pp.eb = pp.ec;   pp.ec = he;
    // v1 row gv = j-1 (step-1 output, re-zero-padded)
    float4 v;
    v.x = P_ * (pp.h1a.x + pp.h1c.x) + Q_ * pp.h1b.x;
    v.y = P_ * (pp.h1a.y + pp.h1c.y) + Q_ * pp.h1b.y;
    v.z = P_ * (pp.h1a.z + pp.h1c.z) + Q_ * pp.h1b.z;
    v.w = P_ * (pp.h1a.w + pp.h1c.w) + Q_ * pp.h1b.w;
    float ve = P_ * (pp.ea + pp.ec) + Q_ * pp.eb;
    if ((unsigned)gv >= HH) { v = make_float4(0.f, 0.f, 0.f, 0.f); ve = 0.f; }
    if (lane == 0 && xlo)  ve = 0.f;   // col -1 outside image
    if (lane == 31 && xhi) ve = 0.f;   // col 1024 outside image
    // h2 row gv
    float vl = __shfl_up_sync(WFULL, v.w, 1);   if (lane == 0)  vl = ve;
    float vr = __shfl_down_sync(WFULL, v.x, 1); if (lane == 31) vr = ve;
    float4 g;
    g.x = P_ * (vl + v.y) + Q_ * v.x;
    g.y = P_ * (v.x + v.z) + Q_ * v.y;
    g.z = P_ * (v.y + v.w) + Q_ * v.z;
    g.w = P_ * (v.z + vr) + Q_ * v.w;
    pp.h2a = pp.h2b; pp.h2b = pp.h2c; pp.h2c = g;
    // out row gv-1 = j-2
    float4 o;
    o.x = P_ * (pp.h2a.x + pp.h2c.x) + Q_ * pp.h2b.x;
    o.y = P_ * (pp.h2a.y + pp.h2c.y) + Q_ * pp.h2b.y;
    o.z = P_ * (pp.h2a.z + pp.h2c.z) + Q_ * pp.h2b.z;
    o.w = P_ * (pp.h2a.w + pp.h2c.w) + Q_ * pp.h2b.w;
    return o;
}

// ---- single-conv pipeline (for the first stats image of each phase) ------
struct SPipe { float4 h1a, h1b, h1c; };

__device__ __forceinline__ float4 sstep(SPipe& pp, float4 x, float e0, float e1,
                                        int lane) {
    float xl = __shfl_up_sync(WFULL, x.w, 1);   if (lane == 0)  xl = e1;
    float xr = __shfl_down_sync(WFULL, x.x, 1); if (lane == 31) xr = e0;
    float4 h;
    h.x = P_ * (xl + x.y) + Q_ * x.x;
    h.y = P_ * (x.x + x.z) + Q_ * x.y;
    h.z = P_ * (x.y + x.w) + Q_ * x.z;
    h.w = P_ * (x.z + xr) + Q_ * x.w;
    pp.h1a = pp.h1b; pp.h1b = pp.h1c; pp.h1c = h;
    float4 o;
    o.x = P_ * (pp.h1a.x + pp.h1c.x) + Q_ * pp.h1b.x;
    o.y = P_ * (pp.h1a.y + pp.h1c.y) + Q_ * pp.h1b.y;
    o.z = P_ * (pp.h1a.z + pp.h1c.z) + Q_ * pp.h1b.z;
    o.w = P_ * (pp.h1a.w + pp.h1c.w) + Q_ * pp.h1b.w;
    return o;
}

// ---- tasks (one warp each: 128x16 output strip) --------------------------
template <int NCH>
__device__ void conv_task(const float* __restrict__ src, float* __restrict__ dst,
                          int x0, int a, int lane, bool xlo, bool xhi) {
    DPipe pp;
#pragma unroll
    for (int i = 0; i < 20; i++) {
        int j = a - 2 + i;
        float e0, e1;
        float4 x = load_row<NCH>(src, j, x0, lane, e0, e1);
        float4 o = dstep(pp, x, e0, e1, lane, j - 1, xlo, xhi);
        if (i >= 4)
            *(float4*)(dst + (size_t)(j - 2) * WW + x0 + lane * 4) = o;
    }
}

__device__ __forceinline__ void mom_acc(float4 ox, float4 oy, float& su, float& su2,
                                        float& sv, float& sv2, float& suv) {
    su  += ox.x + ox.y + ox.z + ox.w;
    su2 += ox.x * ox.x + ox.y * ox.y + ox.z * ox.z + ox.w * ox.w;
    sv  += oy.x + oy.y + oy.z + oy.w;
    sv2 += oy.x * oy.x + oy.y * oy.y + oy.z * oy.z + oy.w * oy.w;
    suv += ox.x * oy.x + ox.y * oy.y + ox.z * oy.z + ox.w * oy.w;
}

__device__ __forceinline__ void mom_emit(float su, float su2, float sv, float sv2,
                                         float suv, int lane, int t, int slot) {
    su = warpSumF(su); su2 = warpSumF(su2); sv = warpSumF(sv);
    sv2 = warpSumF(sv2); suv = warpSumF(suv);
    if (lane == 0) {
        g_part[t][0][slot] = su;  g_part[t][1][slot] = su2;
        g_part[t][2][slot] = sv;  g_part[t][3][slot] = sv2;
        g_part[t][4][slot] = suv;
    }
}

template <int NCH>
__device__ void stats_task_s(const float* __restrict__ sx, const float* __restrict__ sy,
                             int x0, int a, int lane, int t, int slot) {
    SPipe px, py;
    float su = 0, su2 = 0, sv = 0, sv2 = 0, suv = 0;
#pragma unroll
    for (int i = 0; i < 18; i++) {
        int j = a - 1 + i;
        float e0, e1, f0, f1;
        float4 xr_ = load_row<NCH>(sx, j, x0, lane, e0, e1);
        float4 yr_ = load_row<NCH>(sy, j, x0, lane, f0, f1);
        float4 ox = sstep(px, xr_, e0, e1, lane);
        float4 oy = sstep(py, yr_, f0, f1, lane);
        if (i >= 2) mom_acc(ox, oy, su, su2, sv, sv2, suv);
    }
    mom_emit(su, su2, sv, sv2, suv, lane, t, slot);
}

template <int NCH>
__device__ void stats_task_d(const float* __restrict__ sx, const float* __restrict__ sy,
                             int x0, int a, int lane, bool xlo, bool xhi,
                             int t, int slot) {
    DPipe px, py;
    float su = 0, su2 = 0, sv = 0, sv2 = 0, suv = 0;
#pragma unroll
    for (int i = 0; i < 20; i++) {
        int j = a - 2 + i;
        float e0, e1, f0, f1;
        float4 xr_ = load_row<NCH>(sx, j, x0, lane, e0, e1);
        float4 yr_ = load_row<NCH>(sy, j, x0, lane, f0, f1);
        float4 ox = dstep(px, xr_, e0, e1, lane, j - 1, xlo, xhi);
        float4 oy = dstep(py, yr_, f0, f1, lane, j - 1, xlo, xhi);
        if (i >= 4) mom_acc(ox, oy, su, su2, sv, sv2, suv);
    }
    mom_emit(su, su2, sv, sv2, suv, lane, t, slot);
}

// ---- global software barrier ---------------------------------------------
__device__ __forceinline__ void gbar(int nblocks, unsigned phase, int tid) {
    __syncthreads();
    if (tid == 0) {
        __threadfence();
        unsigned c = atomicAdd(&g_barcnt, 1u);
        if (c == (unsigned)nblocks - 1u) {
            g_barcnt = 0;
            __threadfence();
            g_sense = phase;
        } else {
            while (g_sense < phase) __nanosleep(64);
            __threadfence();
        }
    }
    __syncthreads();
}

// ---- finalize: 8 SSIM terms in double (block 0) --------------------------
__device__ void finalize_dev(float* __restrict__ out, int tid) {
    __shared__ double sm[NB][5];
    const int w = tid >> 5, lane = tid & 31;
    for (int idx = w; idx < NB * 5; idx += 8) {
        int t = idx / 5, m = idx - 5 * t;
        double s = 0.0;
        for (int b = lane; b < NBLK; b += 32) s += (double)g_part[t][m][b];
        s = warpSumD(s);
        if (lane == 0) sm[t][m] = s;
    }
    __syncthreads();
    if (tid == 0) {
        double tot = 0.0, sc = 1.0;
        const double N = (double)NPIX;
        const double C1 = 6.5025;    // (0.01*255)^2
        const double C2 = 58.5225;   // (0.03*255)^2
        for (int t = 0; t < NB; t++) {
            double SU = sm[t][0], SU2 = sm[t][1], SV = sm[t][2],
                   SV2 = sm[t][3], SUV = sm[t][4];
            double mu = sc * SU / N;
            double mv = sc * SV / N;
            double varu = sc * sc * (SU2 - SU * SU / N) / (N - 1.0);
            double varv = sc * sc * (SV2 - SV * SV / N) / (N - 1.0);
            double cov  = sc * sc * (SUV - SU * SV / N) / (N - 1.0);
            tot += ((2.0 * mu * mv + C1) * (2.0 * cov + C2)) /
                   ((mu * mu + mv * mv + C1) * (varu * varu + varv * varv + C2));
            sc *= 3.0;   // 3^t channel-mixing gain
        }
        out[0] = (float)tot;
    }
}

// ---------------------------------------------------------------------------
// Persistent kernel: 4 pair-phases with global barriers; warp-level tasks.
// Task = (plane, 128x128 tile); warp w sweeps rows [tile_y + 16w, +16).
// ---------------------------------------------------------------------------
__global__ void __launch_bounds__(256, 2)
ssim_persist(const float* __restrict__ xin, const float* __restrict__ yin,
             float* __restrict__ out, int nblocks) {
    const int tid = threadIdx.x, lane = tid & 31, w = tid >> 5;

    for (int p = 0; p < 4; p++) {
        const int t0 = 2 * p, nimg = NB - t0;
        const int rp = (p & 1) ^ 1, wp = p & 1;
        const int ntasks = (2 + 2 * (nimg - 2)) * 64;

        for (int task = blockIdx.x; task < ntasks; task += nblocks) {
            const int plane = task >> 6, tile = task & 63;
            const int x0 = (tile & 7) * 128;
            const int a  = (tile >> 3) * 128 + w * 16;
            const bool xlo = (x0 == 0), xhi = (x0 == WW - 128);
            const int slot = tile * 8 + w;

            if (plane < 2) {
                const int t = t0 + plane;
                const float *sx, *sy;
                if (p == 0) {
                    sx = xin + (size_t)t * 3 * NPIX;
                    sy = yin + (size_t)t * 3 * NPIX;
                } else {
                    sx = g_buf[rp][0] + (size_t)t * NPIX;
                    sy = g_buf[rp][1] + (size_t)t * NPIX;
                }
                if (plane == 0) {
                    if (p == 0) stats_task_s<3>(sx, sy, x0, a, lane, t, slot);
                    else        stats_task_s<1>(sx, sy, x0, a, lane, t, slot);
                } else {
                    if (p == 0) stats_task_d<3>(sx, sy, x0, a, lane, xlo, xhi, t, slot);
                    else        stats_task_d<1>(sx, sy, x0, a, lane, xlo, xhi, t, slot);
                }
            } else {
                int q = plane - 2;
                int xy = (q >= nimg - 2) ? 1 : 0;
                int img = t0 + 2 + q - xy * (nimg - 2);
                const float* src = (p == 0)
                    ? ((xy ? yin : xin) + (size_t)img * 3 * NPIX)
                    : (g_buf[rp][xy] + (size_t)img * NPIX);
                float* dst = g_buf[wp][xy] + (size_t)img * NPIX;
                if (p == 0) conv_task<3>(src, dst, x0, a, lane, xlo, xhi);
                else        conv_task<1>(src, dst, x0, a, lane, xlo, xhi);
            }
        }
        gbar(nblocks, (unsigned)(p + 1), tid);
    }

    if (blockIdx.x == 0) {
        finalize_dev(out, tid);
        if (tid == 0) {
            __threadfence();
            g_sense = 0;   // reset for next graph replay
        }
    }
}

// ---------------------------------------------------------------------------
extern "C" void kernel_launch(void* const* d_in, const int* in_sizes, int n_in,
                              void* d_out, int out_size) {
    const float* x = (const float*)d_in[0];
    const float* y = (const float*)d_in[1];
    float* out = (float*)d_out;

    int dev = 0;
    cudaGetDevice(&dev);
    int sms = 148;
    cudaDeviceGetAttribute(&sms, cudaDevAttrMultiProcessorCount, dev);
    int occ = 1;
    cudaOccupancyMaxActiveBlocksPerMultiprocessor(&occ, ssim_persist, 256, 0);
    if (occ < 1) occ = 1;
    int nblocks = sms * occ;

    ssim_persist<<<nblocks, 256>>>(x, y, out, nblocks);
}

// round 9
// speedup vs baseline: 1.2343x; 1.2343x over previous
#include <cuda_runtime.h>

#define HH 1024
#define WW 1024
#define NPIX (HH * WW)
#define NB 8
#define NBLK 512   // tiles per plane: 8 x 64 (128x16 tiles)

#define P_ 0.19487471f   // sqrt(0.03797616)
#define Q_ 0.23021729f   // sqrt(0.053); outer([p,q,p],[p,q,p]) == reference 3x3
#define WFULL 0xffffffffu

__device__ float    g_buf[2][2][NB * NPIX];
__device__ float    g_part[NB][5][NBLK];
__device__ unsigned g_barcnt;
__device__ volatile unsigned g_sense;

struct Tile {
    float h1[20][128];
    float h2[18][128];
    float elo[20], ehi[20];
    float red[5][8];
};

__inline__ __device__ float warpSumF(float v) {
#pragma unroll
    for (int o = 16; o; o >>= 1) v += __shfl_down_sync(WFULL, v, o);
    return v;
}
__inline__ __device__ double warpSumD(double v) {
#pragma unroll
    for (int o = 16; o; o >>= 1) v += __shfl_down_sync(WFULL, v, o);
    return v;
}

__device__ __forceinline__ float4 vpass(float4 a, float4 b, float4 c) {
    return make_float4(P_ * (a.x + c.x) + Q_ * b.x,
                       P_ * (a.y + c.y) + Q_ * b.y,
                       P_ * (a.z + c.z) + Q_ * b.z,
                       P_ * (a.w + c.w) + Q_ * b.w);
}

// ---- row load: thread's float4 of row gy + edge scalars for lanes 0/31 ----
template <int NCH>
__device__ __forceinline__ float4 load_row(const float* __restrict__ s, int gy,
                                           int x0, int lane, float& e0, float& e1) {
    e0 = 0.f; e1 = 0.f;
    if ((unsigned)gy >= HH) return make_float4(0.f, 0.f, 0.f, 0.f);
    const float* r = s + (size_t)gy * WW;
    const float* q = r + x0 + lane * 4;
    float4 a = *(const float4*)q;
    if (NCH == 3) {
        float4 b = *(const float4*)(q + NPIX);
        float4 c = *(const float4*)(q + 2 * NPIX);
        a.x += b.x + c.x; a.y += b.y + c.y; a.z += b.z + c.z; a.w += b.w + c.w;
    }
    if (lane == 0) {
        if (x0 > 0) {
            e0 = r[x0 - 2]; e1 = r[x0 - 1];
            if (NCH == 3) {
                e0 += r[x0 - 2 + NPIX] + r[x0 - 2 + 2 * NPIX];
                e1 += r[x0 - 1 + NPIX] + r[x0 - 1 + 2 * NPIX];
            }
        }
    } else if (lane == 31) {
        if (x0 < WW - 128) {
            e0 = r[x0 + 128]; e1 = r[x0 + 129];
            if (NCH == 3) {
                e0 += r[x0 + 128 + NPIX] + r[x0 + 128 + 2 * NPIX];
                e1 += r[x0 + 129 + NPIX] + r[x0 + 129 + 2 * NPIX];
            }
        }
    }
    return a;
}

// ---- horizontal conv of a register row via shuffles ----------------------
__device__ __forceinline__ float4 hshuf(float4 x, float e0, float e1, int lane) {
    float xl = __shfl_up_sync(WFULL, x.w, 1);   if (lane == 0)  xl = e1;
    float xr = __shfl_down_sync(WFULL, x.x, 1); if (lane == 31) xr = e0;
    return make_float4(P_ * (xl + x.y) + Q_ * x.x,
                       P_ * (x.x + x.z) + Q_ * x.y,
                       P_ * (x.y + x.w) + Q_ * x.z,
                       P_ * (x.z + xr) + Q_ * x.w);
}

// ---- H1 phase, double conv: 20 rows (gy=y0-2+r), with edge columns -------
template <int NCH>
__device__ __forceinline__ void h1_double(Tile* S, const float* __restrict__ src,
                                          int x0, int y0, int lane, int w) {
#pragma unroll
    for (int k = 0; k < 3; k++) {
        int r = w + 8 * k;
        if (r < 20) {
            float e0, e1;
            float4 x = load_row<NCH>(src, y0 - 2 + r, x0, lane, e0, e1);
            float4 h = hshuf(x, e0, e1, lane);
            *(float4*)&S->h1[r][4 * lane] = h;
            // h1 at col -1: x[-2]=e0, x[-1]=e1, x[0]=x.x (lane0)
            if (lane == 0)  S->elo[r] = P_ * (e0 + x.x) + Q_ * e1;
            // h1 at col 128: x[127]=x.w, x[128]=e0, x[129]=e1 (lane31)
            if (lane == 31) S->ehi[r] = P_ * (x.w + e1) + Q_ * e0;
        }
    }
}

// ---- H1 phase, single conv: 18 rows (gy=y0-1+r), no edges needed ---------
template <int NCH>
__device__ __forceinline__ void h1_single(Tile* S, const float* __restrict__ src,
                                          int x0, int y0, int lane, int w) {
#pragma unroll
    for (int k = 0; k < 3; k++) {
        int r = w + 8 * k;
        if (r < 18) {
            float e0, e1;
            float4 x = load_row<NCH>(src, y0 - 1 + r, x0, lane, e0, e1);
            *(float4*)&S->h1[r][4 * lane] = hshuf(x, e0, e1, lane);
        }
    }
}

// ---- V1 + re-zero-pad mask + H2 (shuffle) --------------------------------
__device__ __forceinline__ void v1h2(Tile* S, int y0, int lane, int w,
                                     bool xlo, bool xhi) {
#pragma unroll
    for (int k = 0; k < 3; k++) {
        int rv = w + 8 * k;
        if (rv < 18) {
            float4 b0 = *(float4*)&S->h1[rv][4 * lane];
            float4 b1 = *(float4*)&S->h1[rv + 1][4 * lane];
            float4 b2 = *(float4*)&S->h1[rv + 2][4 * lane];
            float4 v = vpass(b0, b1, b2);
            float ve = 0.f;
            if (lane == 0)
                ve = P_ * (S->elo[rv] + S->elo[rv + 2]) + Q_ * S->elo[rv + 1];
            else if (lane == 31)
                ve = P_ * (S->ehi[rv] + S->ehi[rv + 2]) + Q_ * S->ehi[rv + 1];
            int gv = y0 - 1 + rv;
            if ((unsigned)gv >= HH) { v = make_float4(0.f, 0.f, 0.f, 0.f); ve = 0.f; }
            if (lane == 0 && xlo)  ve = 0.f;   // col -1 outside image
            if (lane == 31 && xhi) ve = 0.f;   // col 1024 outside image
            float vl = __shfl_up_sync(WFULL, v.w, 1);   if (lane == 0)  vl = ve;
            float vr = __shfl_down_sync(WFULL, v.x, 1); if (lane == 31) vr = ve;
            float4 g;
            g.x = P_ * (vl + v.y) + Q_ * v.x;
            g.y = P_ * (v.x + v.z) + Q_ * v.y;
            g.z = P_ * (v.y + v.w) + Q_ * v.z;
            g.w = P_ * (v.z + vr) + Q_ * v.w;
            *(float4*)&S->h2[rv][4 * lane] = g;
        }
    }
}

__device__ __forceinline__ float4 v2_h2(Tile* S, int ro, int tx) {
    return vpass(*(float4*)&S->h2[ro][4 * tx],
                 *(float4*)&S->h2[ro + 1][4 * tx],
                 *(float4*)&S->h2[ro + 2][4 * tx]);
}
__device__ __forceinline__ float4 v2_h1(Tile* S, int ro, int tx) {
    return vpass(*(float4*)&S->h1[ro][4 * tx],
                 *(float4*)&S->h1[ro + 1][4 * tx],
                 *(float4*)&S->h1[ro + 2][4 * tx]);
}

// ---- whole-tile convs: outputs 2 float4 per thread (rows 2w, 2w+1) -------
template <int NCH>
__device__ __forceinline__ void dconv_tile(Tile* S, const float* __restrict__ src,
                                           int x0, int y0, int lane, int w,
                                           bool xlo, bool xhi, float4 o[2]) {
    __syncthreads();   // protect smem reuse from previous task/phase
    h1_double<NCH>(S, src, x0, y0, lane, w);
    __syncthreads();
    v1h2(S, y0, lane, w, xlo, xhi);
    __syncthreads();
    o[0] = v2_h2(S, 2 * w, lane);
    o[1] = v2_h2(S, 2 * w + 1, lane);
}

template <int NCH>
__device__ __forceinline__ void sconv_tile(Tile* S, const float* __restrict__ src,
                                           int x0, int y0, int lane, int w,
                                           float4 o[2]) {
    __syncthreads();
    h1_single<NCH>(S, src, x0, y0, lane, w);
    __syncthreads();
    o[0] = v2_h1(S, 2 * w, lane);
    o[1] = v2_h1(S, 2 * w + 1, lane);
}

// ---- moments -------------------------------------------------------------
__device__ __forceinline__ void mom_acc(float4 a, float4 b, float& su, float& su2,
                                        float& sv, float& sv2, float& suv) {
    su  += a.x + a.y + a.z + a.w;
    su2 += a.x * a.x + a.y * a.y + a.z * a.z + a.w * a.w;
    sv  += b.x + b.y + b.z + b.w;
    sv2 += b.x * b.x + b.y * b.y + b.z * b.z + b.w * b.w;
    suv += a.x * b.x + a.y * b.y + a.z * b.z + a.w * b.w;
}

__device__ __forceinline__ void mom_emit(Tile* S, float su, float su2, float sv,
                                         float sv2, float suv, int lane, int w,
                                         int tid, int t, int tile) {
    su = warpSumF(su); su2 = warpSumF(su2); sv = warpSumF(sv);
    sv2 = warpSumF(sv2); suv = warpSumF(suv);
    if (lane == 0) {
        S->red[0][w] = su; S->red[1][w] = su2; S->red[2][w] = sv;
        S->red[3][w] = sv2; S->red[4][w] = suv;
    }
    __syncthreads();
    if (tid < 5) {
        float r = 0.f;
#pragma unroll
        for (int q = 0; q < 8; q++) r += S->red[tid][q];
        g_part[t][tid][tile] = r;
    }
}

// ---- global software barrier ---------------------------------------------
__device__ __forceinline__ void gbar(int nblocks, unsigned phase, int tid) {
    __syncthreads();
    if (tid == 0) {
        __threadfence();
        unsigned c = atomicAdd(&g_barcnt, 1u);
        if (c == (unsigned)nblocks - 1u) {
            g_barcnt = 0;
            __threadfence();
            g_sense = phase;
        } else {
            while (g_sense < phase) __nanosleep(64);
            __threadfence();
        }
    }
    __syncthreads();
}

// ---- finalize: 8 SSIM terms in double (block 0) --------------------------
__device__ void finalize_dev(float* __restrict__ out, int tid) {
    __shared__ double smd[NB][5];
    const int w = tid >> 5, lane = tid & 31;
    for (int idx = w; idx < NB * 5; idx += 8) {
        int t = idx / 5, m = idx - 5 * t;
        double s = 0.0;
        for (int b = lane; b < NBLK; b += 32) s += (double)g_part[t][m][b];
        s = warpSumD(s);
        if (lane == 0) smd[t][m] = s;
    }
    __syncthreads();
    if (tid == 0) {
        double tot = 0.0, sc = 1.0;
        const double N = (double)NPIX;
        const double C1 = 6.5025;    // (0.01*255)^2
        const double C2 = 58.5225;   // (0.03*255)^2
        for (int t = 0; t < NB; t++) {
            double SU = smd[t][0], SU2 = smd[t][1], SV = smd[t][2],
                   SV2 = smd[t][3], SUV = smd[t][4];
            double mu = sc * SU / N;
            double mv = sc * SV / N;
            double varu = sc * sc * (SU2 - SU * SU / N) / (N - 1.0);
            double varv = sc * sc * (SV2 - SV * SV / N) / (N - 1.0);
            double cov  = sc * sc * (SUV - SU * SV / N) / (N - 1.0);
            tot += ((2.0 * mu * mv + C1) * (2.0 * cov + C2)) /
                   ((mu * mu + mv * mv + C1) * (varu * varu + varv * varv + C2));
            sc *= 3.0;   // 3^t channel-mixing gain
        }
        out[0] = (float)tot;
    }
}

// ---------------------------------------------------------------------------
// Persistent kernel: 4 pair-phases with global barriers; block tasks of
// 128x16 output tiles. Phase p (t0=2p): planes 0/1 = stats images t0,t0+1
// (no plane writes); planes >=2 = double conv of future images (ping-pong).
// ---------------------------------------------------------------------------
__global__ void __launch_bounds__(256, 4)
ssim_persist(const float* __restrict__ xin, const float* __restrict__ yin,
             float* __restrict__ out, int nblocks) {
    __shared__ Tile S;
    const int tid = threadIdx.x, lane = tid & 31, w = tid >> 5;

    for (int p = 0; p < 4; p++) {
        const int t0 = 2 * p, nimg = NB - t0;
        const int rp = (p & 1) ^ 1, wp = p & 1;
        const int ntasks = (2 + 2 * (nimg - 2)) * NBLK;

        for (int task = blockIdx.x; task < ntasks; task += nblocks) {
            const int plane = task >> 9, tile = task & 511;
            const int x0 = (tile & 7) * 128;
            const int y0 = (tile >> 3) * 16;
            const bool xlo = (x0 == 0), xhi = (x0 == WW - 128);

            if (plane >= 2) {
                int q = plane - 2;
                int xy = (q >= nimg - 2) ? 1 : 0;
                int img = t0 + 2 + q - xy * (nimg - 2);
                const float* src = (p == 0)
                    ? ((xy ? yin : xin) + (size_t)img * 3 * NPIX)
                    : (g_buf[rp][xy] + (size_t)img * NPIX);
                float* dst = g_buf[wp][xy] + (size_t)img * NPIX;
                float4 o[2];
                if (p == 0) dconv_tile<3>(&S, src, x0, y0, lane, w, xlo, xhi, o);
                else        dconv_tile<1>(&S, src, x0, y0, lane, w, xlo, xhi, o);
                *(float4*)(dst + (size_t)(y0 + 2 * w) * WW + x0 + 4 * lane) = o[0];
                *(float4*)(dst + (size_t)(y0 + 2 * w + 1) * WW + x0 + 4 * lane) = o[1];
            } else {
                const int t = t0 + plane;
                const float *sx, *sy;
                if (p == 0) {
                    sx = xin + (size_t)t * 3 * NPIX;
                    sy = yin + (size_t)t * 3 * NPIX;
                } else {
                    sx = g_buf[rp][0] + (size_t)t * NPIX;
                    sy = g_buf[rp][1] + (size_t)t * NPIX;
                }
                float4 ox[2], oy[2];
                if (plane == 0) {
                    if (p == 0) { sconv_tile<3>(&S, sx, x0, y0, lane, w, ox);
                                  sconv_tile<3>(&S, sy, x0, y0, lane, w, oy); }
                    else        { sconv_tile<1>(&S, sx, x0, y0, lane, w, ox);
                                  sconv_tile<1>(&S, sy, x0, y0, lane, w, oy); }
                } else {
                    if (p == 0) { dconv_tile<3>(&S, sx, x0, y0, lane, w, xlo, xhi, ox);
                                  dconv_tile<3>(&S, sy, x0, y0, lane, w, xlo, xhi, oy); }
                    else        { dconv_tile<1>(&S, sx, x0, y0, lane, w, xlo, xhi, ox);
                                  dconv_tile<1>(&S, sy, x0, y0, lane, w, xlo, xhi, oy); }
                }
                float su = 0, su2 = 0, sv = 0, sv2 = 0, suv = 0;
                mom_acc(ox[0], oy[0], su, su2, sv, sv2, suv);
                mom_acc(ox[1], oy[1], su, su2, sv, sv2, suv);
                mom_emit(&S, su, su2, sv, sv2, suv, lane, w, tid, t, tile);
            }
        }
        gbar(nblocks, (unsigned)(p + 1), tid);
    }

    if (blockIdx.x == 0) {
        finalize_dev(out, tid);
        if (tid == 0) {
            __threadfence();
            g_sense = 0;   // reset for next graph replay
        }
    }
}

// ---------------------------------------------------------------------------
extern "C" void kernel_launch(void* const* d_in, const int* in_sizes, int n_in,
                              void* d_out, int out_size) {
    const float* x = (const float*)d_in[0];
    const float* y = (const float*)d_in[1];
    float* out = (float*)d_out;

    int dev = 0;
    cudaGetDevice(&dev);
    int sms = 148;
    cudaDeviceGetAttribute(&sms, cudaDevAttrMultiProcessorCount, dev);
    int occ = 1;
    cudaOccupancyMaxActiveBlocksPerMultiprocessor(&occ, ssim_persist, 256, 0);
    if (occ < 1) occ = 1;
    int nblocks = sms * occ;

    ssim_persist<<<nblocks, 256>>>(x, y, out, nblocks);
}

// round 10
// speedup vs baseline: 1.3180x; 1.0678x over previous
#include <cuda_runtime.h>

#define HH 1024
#define WW 1024
#define NPIX (HH * WW)
#define NB 8
#define NBLK 256   // tiles per plane: 8 x 32 (128x32 tiles)

#define P_ 0.19487471f   // sqrt(0.03797616)
#define Q_ 0.23021729f   // sqrt(0.053); outer([p,q,p],[p,q,p]) == reference 3x3
#define WFULL 0xffffffffu

__device__ float    g_buf[2][2][NB * NPIX];
__device__ float    g_part[NB][5][NBLK];
__device__ unsigned g_barcnt;
__device__ volatile unsigned g_sense;

struct Tile {
    float h1[36][128];   // double conv: rows gy = y0-2 .. y0+33
    float h2[34][128];   // rows gv = y0-1 .. y0+32
    float elo[36], ehi[36];
    float red[5][8];
};

__inline__ __device__ float warpSumF(float v) {
#pragma unroll
    for (int o = 16; o; o >>= 1) v += __shfl_down_sync(WFULL, v, o);
    return v;
}
__inline__ __device__ double warpSumD(double v) {
#pragma unroll
    for (int o = 16; o; o >>= 1) v += __shfl_down_sync(WFULL, v, o);
    return v;
}

__device__ __forceinline__ float4 vpass(float4 a, float4 b, float4 c) {
    return make_float4(P_ * (a.x + c.x) + Q_ * b.x,
                       P_ * (a.y + c.y) + Q_ * b.y,
                       P_ * (a.z + c.z) + Q_ * b.z,
                       P_ * (a.w + c.w) + Q_ * b.w);
}

// ---- row load: thread's float4 of row gy + edge scalars for lanes 0/31 ----
template <int NCH>
__device__ __forceinline__ float4 load_row(const float* __restrict__ s, int gy,
                                           int x0, int lane, float& e0, float& e1) {
    e0 = 0.f; e1 = 0.f;
    if ((unsigned)gy >= HH) return make_float4(0.f, 0.f, 0.f, 0.f);
    const float* r = s + (size_t)gy * WW;
    const float* q = r + x0 + lane * 4;
    float4 a = *(const float4*)q;
    if (NCH == 3) {
        float4 b = *(const float4*)(q + NPIX);
        float4 c = *(const float4*)(q + 2 * NPIX);
        a.x += b.x + c.x; a.y += b.y + c.y; a.z += b.z + c.z; a.w += b.w + c.w;
    }
    if (lane == 0) {
        if (x0 > 0) {
            e0 = r[x0 - 2]; e1 = r[x0 - 1];
            if (NCH == 3) {
                e0 += r[x0 - 2 + NPIX] + r[x0 - 2 + 2 * NPIX];
                e1 += r[x0 - 1 + NPIX] + r[x0 - 1 + 2 * NPIX];
            }
        }
    } else if (lane == 31) {
        if (x0 < WW - 128) {
            e0 = r[x0 + 128]; e1 = r[x0 + 129];
            if (NCH == 3) {
                e0 += r[x0 + 128 + NPIX] + r[x0 + 128 + 2 * NPIX];
                e1 += r[x0 + 129 + NPIX] + r[x0 + 129 + 2 * NPIX];
            }
        }
    }
    return a;
}

// ---- horizontal conv of a register row via shuffles ----------------------
__device__ __forceinline__ float4 hshuf(float4 x, float e0, float e1, int lane) {
    float xl = __shfl_up_sync(WFULL, x.w, 1);   if (lane == 0)  xl = e1;
    float xr = __shfl_down_sync(WFULL, x.x, 1); if (lane == 31) xr = e0;
    return make_float4(P_ * (xl + x.y) + Q_ * x.x,
                       P_ * (x.x + x.z) + Q_ * x.y,
                       P_ * (x.y + x.w) + Q_ * x.z,
                       P_ * (x.z + xr) + Q_ * x.w);
}

// ---- H1, double conv: 36 rows (gy=y0-2+r) with edge columns --------------
template <int NCH>
__device__ __forceinline__ void h1_double(Tile* S, const float* __restrict__ src,
                                          int x0, int y0, int lane, int w) {
#pragma unroll
    for (int k = 0; k < 5; k++) {
        int r = w + 8 * k;
        if (r < 36) {
            float e0, e1;
            float4 x = load_row<NCH>(src, y0 - 2 + r, x0, lane, e0, e1);
            float4 h = hshuf(x, e0, e1, lane);
            *(float4*)&S->h1[r][4 * lane] = h;
            if (lane == 0)  S->elo[r] = P_ * (e0 + x.x) + Q_ * e1;  // col -1
            if (lane == 31) S->ehi[r] = P_ * (x.w + e1) + Q_ * e0;  // col 128
        }
    }
}

// ---- H1, single conv: 34 rows (gy=y0-1+r), no edges ----------------------
template <int NCH>
__device__ __forceinline__ void h1_single(Tile* S, const float* __restrict__ src,
                                          int x0, int y0, int lane, int w) {
#pragma unroll
    for (int k = 0; k < 5; k++) {
        int r = w + 8 * k;
        if (r < 34) {
            float e0, e1;
            float4 x = load_row<NCH>(src, y0 - 1 + r, x0, lane, e0, e1);
            *(float4*)&S->h1[r][4 * lane] = hshuf(x, e0, e1, lane);
        }
    }
}

// ---- V1 + re-zero-pad + H2 (shuffle): 34 rows ----------------------------
__device__ __forceinline__ void v1h2(Tile* S, int y0, int lane, int w,
                                     bool xlo, bool xhi) {
#pragma unroll
    for (int k = 0; k < 5; k++) {
        int rv = w + 8 * k;
        if (rv < 34) {
            float4 b0 = *(float4*)&S->h1[rv][4 * lane];
            float4 b1 = *(float4*)&S->h1[rv + 1][4 * lane];
            float4 b2 = *(float4*)&S->h1[rv + 2][4 * lane];
            float4 v = vpass(b0, b1, b2);
            float ve = 0.f;
            if (lane == 0)
                ve = P_ * (S->elo[rv] + S->elo[rv + 2]) + Q_ * S->elo[rv + 1];
            else if (lane == 31)
                ve = P_ * (S->ehi[rv] + S->ehi[rv + 2]) + Q_ * S->ehi[rv + 1];
            int gv = y0 - 1 + rv;
            if ((unsigned)gv >= HH) { v = make_float4(0.f, 0.f, 0.f, 0.f); ve = 0.f; }
            if (lane == 0 && xlo)  ve = 0.f;   // col -1 outside image
            if (lane == 31 && xhi) ve = 0.f;   // col 1024 outside image
            float vl = __shfl_up_sync(WFULL, v.w, 1);   if (lane == 0)  vl = ve;
            float vr = __shfl_down_sync(WFULL, v.x, 1); if (lane == 31) vr = ve;
            float4 g;
            g.x = P_ * (vl + v.y) + Q_ * v.x;
            g.y = P_ * (v.x + v.z) + Q_ * v.y;
            g.z = P_ * (v.y + v.w) + Q_ * v.z;
            g.w = P_ * (v.z + vr) + Q_ * v.w;
            *(float4*)&S->h2[rv][4 * lane] = g;
        }
    }
}

__device__ __forceinline__ float4 v2_h2(Tile* S, int ro, int tx) {
    return vpass(*(float4*)&S->h2[ro][4 * tx],
                 *(float4*)&S->h2[ro + 1][4 * tx],
                 *(float4*)&S->h2[ro + 2][4 * tx]);
}
__device__ __forceinline__ float4 v2_h1(Tile* S, int ro, int tx) {
    return vpass(*(float4*)&S->h1[ro][4 * tx],
                 *(float4*)&S->h1[ro + 1][4 * tx],
                 *(float4*)&S->h1[ro + 2][4 * tx]);
}

// ---- whole-tile convs: 4 float4 outputs/thread (rows 4w..4w+3) -----------
template <int NCH>
__device__ __forceinline__ void dconv_tile(Tile* S, const float* __restrict__ src,
                                           int x0, int y0, int lane, int w,
                                           bool xlo, bool xhi, float4 o[4]) {
    __syncthreads();   // protect smem reuse from previous task
    h1_double<NCH>(S, src, x0, y0, lane, w);
    __syncthreads();
    v1h2(S, y0, lane, w, xlo, xhi);
    __syncthreads();
#pragma unroll
    for (int j = 0; j < 4; j++) o[j] = v2_h2(S, 4 * w + j, lane);
}

template <int NCH>
__device__ __forceinline__ void sconv_tile(Tile* S, const float* __restrict__ src,
                                           int x0, int y0, int lane, int w,
                                           float4 o[4]) {
    __syncthreads();
    h1_single<NCH>(S, src, x0, y0, lane, w);
    __syncthreads();
#pragma unroll
    for (int j = 0; j < 4; j++) o[j] = v2_h1(S, 4 * w + j, lane);
}

// ---- moments -------------------------------------------------------------
__device__ __forceinline__ void mom_acc(float4 a, float4 b, float& su, float& su2,
                                        float& sv, float& sv2, float& suv) {
    su  += a.x + a.y + a.z + a.w;
    su2 += a.x * a.x + a.y * a.y + a.z * a.z + a.w * a.w;
    sv  += b.x + b.y + b.z + b.w;
    sv2 += b.x * b.x + b.y * b.y + b.z * b.z + b.w * b.w;
    suv += a.x * b.x + a.y * b.y + a.z * b.z + a.w * b.w;
}

__device__ __forceinline__ void mom_emit(Tile* S, float su, float su2, float sv,
                                         float sv2, float suv, int lane, int w,
                                         int tid, int t, int tile) {
    su = warpSumF(su); su2 = warpSumF(su2); sv = warpSumF(sv);
    sv2 = warpSumF(sv2); suv = warpSumF(suv);
    if (lane == 0) {
        S->red[0][w] = su; S->red[1][w] = su2; S->red[2][w] = sv;
        S->red[3][w] = sv2; S->red[4][w] = suv;
    }
    __syncthreads();
    if (tid < 5) {
        float r = 0.f;
#pragma unroll
        for (int q = 0; q < 8; q++) r += S->red[tid][q];
        g_part[t][tid][tile] = r;
    }
}

// ---- global software barrier ---------------------------------------------
__device__ __forceinline__ void gbar(int nblocks, unsigned phase, int tid) {
    __syncthreads();
    if (tid == 0) {
        __threadfence();
        unsigned c = atomicAdd(&g_barcnt, 1u);
        if (c == (unsigned)nblocks - 1u) {
            g_barcnt = 0;
            __threadfence();
            g_sense = phase;
        } else {
            while (g_sense < phase) __nanosleep(64);
            __threadfence();
        }
    }
    __syncthreads();
}

// ---- finalize: 8 SSIM terms in double (block 0) --------------------------
__device__ void finalize_dev(float* __restrict__ out, int tid) {
    __shared__ double smd[NB][5];
    const int w = tid >> 5, lane = tid & 31;
    for (int idx = w; idx < NB * 5; idx += 8) {
        int t = idx / 5, m = idx - 5 * t;
        double s = 0.0;
        for (int b = lane; b < NBLK; b += 32) s += (double)g_part[t][m][b];
        s = warpSumD(s);
        if (lane == 0) smd[t][m] = s;
    }
    __syncthreads();
    if (tid == 0) {
        double tot = 0.0, sc = 1.0;
        const double N = (double)NPIX;
        const double C1 = 6.5025;    // (0.01*255)^2
        const double C2 = 58.5225;   // (0.03*255)^2
        for (int t = 0; t < NB; t++) {
            double SU = smd[t][0], SU2 = smd[t][1], SV = smd[t][2],
                   SV2 = smd[t][3], SUV = smd[t][4];
            double mu = sc * SU / N;
            double mv = sc * SV / N;
            double varu = sc * sc * (SU2 - SU * SU / N) / (N - 1.0);
            double varv = sc * sc * (SV2 - SV * SV / N) / (N - 1.0);
            double cov  = sc * sc * (SUV - SU * SV / N) / (N - 1.0);
            tot += ((2.0 * mu * mv + C1) * (2.0 * cov + C2)) /
                   ((mu * mu + mv * mv + C1) * (varu * varu + varv * varv + C2));
            sc *= 3.0;   // 3^t channel-mixing gain
        }
        out[0] = (float)tot;
    }
}

// ---------------------------------------------------------------------------
// Persistent kernel: 4 pair-phases with global barriers; block tasks of
// 128x32 output tiles. Phase p (t0=2p): planes 0/1 = stats images t0,t0+1
// (no plane writes); planes >=2 = double conv of future images (ping-pong).
// ---------------------------------------------------------------------------
__global__ void __launch_bounds__(256, 4)
ssim_persist(const float* __restrict__ xin, const float* __restrict__ yin,
             float* __restrict__ out, int nblocks) {
    __shared__ Tile S;
    const int tid = threadIdx.x, lane = tid & 31, w = tid >> 5;

    for (int p = 0; p < 4; p++) {
        const int t0 = 2 * p, nimg = NB - t0;
        const int rp = (p & 1) ^ 1, wp = p & 1;
        const int ntasks = (2 + 2 * (nimg - 2)) * NBLK;

        for (int task = blockIdx.x; task < ntasks; task += nblocks) {
            const int plane = task >> 8, tile = task & 255;
            const int x0 = (tile & 7) * 128;
            const int y0 = (tile >> 3) * 32;
            const bool xlo = (x0 == 0), xhi = (x0 == WW - 128);

            if (plane >= 2) {
                int q = plane - 2;
                int xy = (q >= nimg - 2) ? 1 : 0;
                int img = t0 + 2 + q - xy * (nimg - 2);
                const float* src = (p == 0)
                    ? ((xy ? yin : xin) + (size_t)img * 3 * NPIX)
                    : (g_buf[rp][xy] + (size_t)img * NPIX);
                float* dst = g_buf[wp][xy] + (size_t)img * NPIX;
                float4 o[4];
                if (p == 0) dconv_tile<3>(&S, src, x0, y0, lane, w, xlo, xhi, o);
                else        dconv_tile<1>(&S, src, x0, y0, lane, w, xlo, xhi, o);
#pragma unroll
                for (int j = 0; j < 4; j++)
                    *(float4*)(dst + (size_t)(y0 + 4 * w + j) * WW + x0 + 4 * lane) = o[j];
            } else {
                const int t = t0 + plane;
                const float *sx, *sy;
                if (p == 0) {
                    sx = xin + (size_t)t * 3 * NPIX;
                    sy = yin + (size_t)t * 3 * NPIX;
                } else {
                    sx = g_buf[rp][0] + (size_t)t * NPIX;
                    sy = g_buf[rp][1] + (size_t)t * NPIX;
                }
                float4 ox[4], oy[4];
                if (plane == 0) {
                    if (p == 0) { sconv_tile<3>(&S, sx, x0, y0, lane, w, ox);
                                  sconv_tile<3>(&S, sy, x0, y0, lane, w, oy); }
                    else        { sconv_tile<1>(&S, sx, x0, y0, lane, w, ox);
                                  sconv_tile<1>(&S, sy, x0, y0, lane, w, oy); }
                } else {
                    if (p == 0) { dconv_tile<3>(&S, sx, x0, y0, lane, w, xlo, xhi, ox);
                                  dconv_tile<3>(&S, sy, x0, y0, lane, w, xlo, xhi, oy); }
                    else        { dconv_tile<1>(&S, sx, x0, y0, lane, w, xlo, xhi, ox);
                                  dconv_tile<1>(&S, sy, x0, y0, lane, w, xlo, xhi, oy); }
                }
                float su = 0, su2 = 0, sv = 0, sv2 = 0, suv = 0;
#pragma unroll
                for (int j = 0; j < 4; j++) mom_acc(ox[j], oy[j], su, su2, sv, sv2, suv);
                mom_emit(&S, su, su2, sv, sv2, suv, lane, w, tid, t, tile);
            }
        }
        gbar(nblocks, (unsigned)(p + 1), tid);
    }

    if (blockIdx.x == 0) {
        finalize_dev(out, tid);
        if (tid == 0) {
            __threadfence();
            g_sense = 0;   // reset for next graph replay
        }
    }
}

// ---------------------------------------------------------------------------
extern "C" void kernel_launch(void* const* d_in, const int* in_sizes, int n_in,
                              void* d_out, int out_size) {
    const float* x = (const float*)d_in[0];
    const float* y = (const float*)d_in[1];
    float* out = (float*)d_out;

    int dev = 0;
    cudaGetDevice(&dev);
    int sms = 148;
    cudaDeviceGetAttribute(&sms, cudaDevAttrMultiProcessorCount, dev);
    int occ = 1;
    cudaOccupancyMaxActiveBlocksPerMultiprocessor(&occ, ssim_persist, 256, 0);
    if (occ < 1) occ = 1;
    int nblocks = sms * occ;

    ssim_persist<<<nblocks, 256>>>(x, y, out, nblocks);
}

// round 11
// speedup vs baseline: 1.3203x; 1.0018x over previous
#include <cuda_runtime.h>

#define HH 1024
#define WW 1024
#define NPIX (HH * WW)
#define NB 8
#define NBLK 256   // tiles per plane: 8 x 32 (128x32 tiles)

#define P_ 0.19487471f   // sqrt(0.03797616)
#define Q_ 0.23021729f   // sqrt(0.053); outer([p,q,p],[p,q,p]) == reference 3x3
#define WFULL 0xffffffffu

__device__ float    g_buf[2][2][NB * NPIX];
__device__ float    g_part[NB][5][NBLK];
__device__ unsigned g_barcnt;
__device__ volatile unsigned g_sense;
__device__ unsigned g_taskctr[4];

struct Tile {
    float h1[36][128];   // rows gy = y0-2 .. y0+33 (double) / y0-1 .. (single)
    float elo[36], ehi[36];
    float red[5][8];
};

__inline__ __device__ float warpSumF(float v) {
#pragma unroll
    for (int o = 16; o; o >>= 1) v += __shfl_down_sync(WFULL, v, o);
    return v;
}
__inline__ __device__ double warpSumD(double v) {
#pragma unroll
    for (int o = 16; o; o >>= 1) v += __shfl_down_sync(WFULL, v, o);
    return v;
}

__device__ __forceinline__ float4 vpass(float4 a, float4 b, float4 c) {
    return make_float4(P_ * (a.x + c.x) + Q_ * b.x,
                       P_ * (a.y + c.y) + Q_ * b.y,
                       P_ * (a.z + c.z) + Q_ * b.z,
                       P_ * (a.w + c.w) + Q_ * b.w);
}

// ---- row load: thread's float4 of row gy + edge scalars for lanes 0/31 ----
template <int NCH>
__device__ __forceinline__ float4 load_row(const float* __restrict__ s, int gy,
                                           int x0, int lane, float& e0, float& e1) {
    e0 = 0.f; e1 = 0.f;
    if ((unsigned)gy >= HH) return make_float4(0.f, 0.f, 0.f, 0.f);
    const float* r = s + (size_t)gy * WW;
    const float* q = r + x0 + lane * 4;
    float4 a = *(const float4*)q;
    if (NCH == 3) {
        float4 b = *(const float4*)(q + NPIX);
        float4 c = *(const float4*)(q + 2 * NPIX);
        a.x += b.x + c.x; a.y += b.y + c.y; a.z += b.z + c.z; a.w += b.w + c.w;
    }
    if (lane == 0) {
        if (x0 > 0) {
            e0 = r[x0 - 2]; e1 = r[x0 - 1];
            if (NCH == 3) {
                e0 += r[x0 - 2 + NPIX] + r[x0 - 2 + 2 * NPIX];
                e1 += r[x0 - 1 + NPIX] + r[x0 - 1 + 2 * NPIX];
            }
        }
    } else if (lane == 31) {
        if (x0 < WW - 128) {
            e0 = r[x0 + 128]; e1 = r[x0 + 129];
            if (NCH == 3) {
                e0 += r[x0 + 128 + NPIX] + r[x0 + 128 + 2 * NPIX];
                e1 += r[x0 + 129 + NPIX] + r[x0 + 129 + 2 * NPIX];
            }
        }
    }
    return a;
}

// ---- horizontal conv of a register row via shuffles ----------------------
__device__ __forceinline__ float4 hshuf(float4 x, float e0, float e1, int lane) {
    float xl = __shfl_up_sync(WFULL, x.w, 1);   if (lane == 0)  xl = e1;
    float xr = __shfl_down_sync(WFULL, x.x, 1); if (lane == 31) xr = e0;
    return make_float4(P_ * (xl + x.y) + Q_ * x.x,
                       P_ * (x.x + x.z) + Q_ * x.y,
                       P_ * (x.y + x.w) + Q_ * x.z,
                       P_ * (x.z + xr) + Q_ * x.w);
}

// ---- H1, double conv: 36 rows (gy=y0-2+r) with edge columns --------------
template <int NCH>
__device__ __forceinline__ void h1_double(Tile* S, const float* __restrict__ src,
                                          int x0, int y0, int lane, int w) {
#pragma unroll
    for (int k = 0; k < 5; k++) {
        int r = w + 8 * k;
        if (r < 36) {
            float e0, e1;
            float4 x = load_row<NCH>(src, y0 - 2 + r, x0, lane, e0, e1);
            float4 h = hshuf(x, e0, e1, lane);
            *(float4*)&S->h1[r][4 * lane] = h;
            if (lane == 0)  S->elo[r] = P_ * (e0 + x.x) + Q_ * e1;  // col -1
            if (lane == 31) S->ehi[r] = P_ * (x.w + e1) + Q_ * e0;  // col 128
        }
    }
}

// ---- H1, single conv: 34 rows (gy=y0-1+r), no edges ----------------------
template <int NCH>
__device__ __forceinline__ void h1_single(Tile* S, const float* __restrict__ src,
                                          int x0, int y0, int lane, int w) {
#pragma unroll
    for (int k = 0; k < 5; k++) {
        int r = w + 8 * k;
        if (r < 34) {
            float e0, e1;
            float4 x = load_row<NCH>(src, y0 - 1 + r, x0, lane, e0, e1);
            *(float4*)&S->h1[r][4 * lane] = hshuf(x, e0, e1, lane);
        }
    }
}

// ---- fused V1 + re-zero-pad + H2 + V2, all in registers per warp ---------
// Warp w produces output rows 4w..4w+3; needs h1 rows 4w..4w+7.
__device__ __forceinline__ void vfused_double(Tile* S, int y0, int lane, int w,
                                              bool xlo, bool xhi, float4 o[4]) {
    float4 g[6];
    float4 a0 = *(float4*)&S->h1[4 * w][4 * lane];
    float4 a1 = *(float4*)&S->h1[4 * w + 1][4 * lane];
#pragma unroll
    for (int m = 0; m < 6; m++) {
        const int rv = 4 * w + m;
        float4 a2 = *(float4*)&S->h1[rv + 2][4 * lane];
        float4 v = vpass(a0, a1, a2);
        float ve = 0.f;
        if (lane == 0)
            ve = P_ * (S->elo[rv] + S->elo[rv + 2]) + Q_ * S->elo[rv + 1];
        else if (lane == 31)
            ve = P_ * (S->ehi[rv] + S->ehi[rv + 2]) + Q_ * S->ehi[rv + 1];
        int gv = y0 - 1 + rv;
        if ((unsigned)gv >= HH) { v = make_float4(0.f, 0.f, 0.f, 0.f); ve = 0.f; }
        if (lane == 0 && xlo)  ve = 0.f;   // col -1 outside image
        if (lane == 31 && xhi) ve = 0.f;   // col 1024 outside image
        float vl = __shfl_up_sync(WFULL, v.w, 1);   if (lane == 0)  vl = ve;
        float vr = __shfl_down_sync(WFULL, v.x, 1); if (lane == 31) vr = ve;
        g[m].x = P_ * (vl + v.y) + Q_ * v.x;
        g[m].y = P_ * (v.x + v.z) + Q_ * v.y;
        g[m].z = P_ * (v.y + v.w) + Q_ * v.z;
        g[m].w = P_ * (v.z + vr) + Q_ * v.w;
        a0 = a1; a1 = a2;
    }
#pragma unroll
    for (int j = 0; j < 4; j++) o[j] = vpass(g[j], g[j + 1], g[j + 2]);
}

// ---- fused V for single conv: out row j needs h1 rows j..j+2 -------------
__device__ __forceinline__ void vfused_single(Tile* S, int lane, int w, float4 o[4]) {
    float4 a0 = *(float4*)&S->h1[4 * w][4 * lane];
    float4 a1 = *(float4*)&S->h1[4 * w + 1][4 * lane];
#pragma unroll
    for (int j = 0; j < 4; j++) {
        float4 a2 = *(float4*)&S->h1[4 * w + j + 2][4 * lane];
        o[j] = vpass(a0, a1, a2);
        a0 = a1; a1 = a2;
    }
}

// ---- whole-tile convs: 4 float4 outputs/thread (rows 4w..4w+3) -----------
template <int NCH>
__device__ __forceinline__ void dconv_tile(Tile* S, const float* __restrict__ src,
                                           int x0, int y0, int lane, int w,
                                           bool xlo, bool xhi, float4 o[4]) {
    __syncthreads();   // protect h1 reuse from previous conv
    h1_double<NCH>(S, src, x0, y0, lane, w);
    __syncthreads();
    vfused_double(S, y0, lane, w, xlo, xhi, o);
}

template <int NCH>
__device__ __forceinline__ void sconv_tile(Tile* S, const float* __restrict__ src,
                                           int x0, int y0, int lane, int w,
                                           float4 o[4]) {
    __syncthreads();
    h1_single<NCH>(S, src, x0, y0, lane, w);
    __syncthreads();
    vfused_single(S, lane, w, o);
}

// ---- moments -------------------------------------------------------------
__device__ __forceinline__ void mom_acc(float4 a, float4 b, float& su, float& su2,
                                        float& sv, float& sv2, float& suv) {
    su  += a.x + a.y + a.z + a.w;
    su2 += a.x * a.x + a.y * a.y + a.z * a.z + a.w * a.w;
    sv  += b.x + b.y + b.z + b.w;
    sv2 += b.x * b.x + b.y * b.y + b.z * b.z + b.w * b.w;
    suv += a.x * b.x + a.y * b.y + a.z * b.z + a.w * b.w;
}

__device__ __forceinline__ void mom_emit(Tile* S, float su, float su2, float sv,
                                         float sv2, float suv, int lane, int w,
                                         int tid, int t, int tile) {
    su = warpSumF(su); su2 = warpSumF(su2); sv = warpSumF(sv);
    sv2 = warpSumF(sv2); suv = warpSumF(suv);
    if (lane == 0) {
        S->red[0][w] = su; S->red[1][w] = su2; S->red[2][w] = sv;
        S->red[3][w] = sv2; S->red[4][w] = suv;
    }
    __syncthreads();
    if (tid < 5) {
        float r = 0.f;
#pragma unroll
        for (int q = 0; q < 8; q++) r += S->red[tid][q];
        g_part[t][tid][tile] = r;
    }
}

// ---- global software barrier ---------------------------------------------
__device__ __forceinline__ void gbar(int nblocks, unsigned phase, int tid) {
    __syncthreads();
    if (tid == 0) {
        __threadfence();
        unsigned c = atomicAdd(&g_barcnt, 1u);
        if (c == (unsigned)nblocks - 1u) {
            g_barcnt = 0;
            __threadfence();
            g_sense = phase;
        } else {
            while (g_sense < phase) __nanosleep(64);
            __threadfence();
        }
    }
    __syncthreads();
}

// ---- finalize: 8 SSIM terms in double (block 0) --------------------------
__device__ void finalize_dev(float* __restrict__ out, int tid) {
    __shared__ double smd[NB][5];
    const int w = tid >> 5, lane = tid & 31;
    for (int idx = w; idx < NB * 5; idx += 8) {
        int t = idx / 5, m = idx - 5 * t;
        double s = 0.0;
        for (int b = lane; b < NBLK; b += 32) s += (double)g_part[t][m][b];
        s = warpSumD(s);
        if (lane == 0) smd[t][m] = s;
    }
    __syncthreads();
    if (tid == 0) {
        double tot = 0.0, sc = 1.0;
        const double N = (double)NPIX;
        const double C1 = 6.5025;    // (0.01*255)^2
        const double C2 = 58.5225;   // (0.03*255)^2
        for (int t = 0; t < NB; t++) {
            double SU = smd[t][0], SU2 = smd[t][1], SV = smd[t][2],
                   SV2 = smd[t][3], SUV = smd[t][4];
            double mu = sc * SU / N;
            double mv = sc * SV / N;
            double varu = sc * sc * (SU2 - SU * SU / N) / (N - 1.0);
            double varv = sc * sc * (SV2 - SV * SV / N) / (N - 1.0);
            double cov  = sc * sc * (SUV - SU * SV / N) / (N - 1.0);
            tot += ((2.0 * mu * mv + C1) * (2.0 * cov + C2)) /
                   ((mu * mu + mv * mv + C1) * (varu * varu + varv * varv + C2));
            sc *= 3.0;   // 3^t channel-mixing gain
        }
        out[0] = (float)tot;
    }
}

// ---------------------------------------------------------------------------
// Persistent kernel: 4 pair-phases with global barriers; work-stealing tasks
// of 128x32 output tiles. Phase p (t0=2p): planes 0/1 = stats images t0,t0+1
// (no plane writes); planes >=2 = double conv of future images (ping-pong).
// ---------------------------------------------------------------------------
__global__ void __launch_bounds__(256, 4)
ssim_persist(const float* __restrict__ xin, const float* __restrict__ yin,
             float* __restrict__ out, int nblocks) {
    __shared__ Tile S;
    __shared__ unsigned s_task;
    const int tid = threadIdx.x, lane = tid & 31, w = tid >> 5;

    for (int p = 0; p < 4; p++) {
        const int t0 = 2 * p, nimg = NB - t0;
        const int rp = (p & 1) ^ 1, wp = p & 1;
        const unsigned ntasks = (unsigned)((2 + 2 * (nimg - 2)) * NBLK);

        for (;;) {
            __syncthreads();
            if (tid == 0) s_task = atomicAdd(&g_taskctr[p], 1u);
            __syncthreads();
            const unsigned task = s_task;
            if (task >= ntasks) break;

            const int plane = task >> 8, tile = task & 255;
            const int x0 = (tile & 7) * 128;
            const int y0 = (tile >> 3) * 32;
            const bool xlo = (x0 == 0), xhi = (x0 == WW - 128);

            if (plane >= 2) {
                int q = plane - 2;
                int xy = (q >= nimg - 2) ? 1 : 0;
                int img = t0 + 2 + q - xy * (nimg - 2);
                const float* src = (p == 0)
                    ? ((xy ? yin : xin) + (size_t)img * 3 * NPIX)
                    : (g_buf[rp][xy] + (size_t)img * NPIX);
                float* dst = g_buf[wp][xy] + (size_t)img * NPIX;
                float4 o[4];
                if (p == 0) dconv_tile<3>(&S, src, x0, y0, lane, w, xlo, xhi, o);
                else        dconv_tile<1>(&S, src, x0, y0, lane, w, xlo, xhi, o);
#pragma unroll
                for (int j = 0; j < 4; j++)
                    *(float4*)(dst + (size_t)(y0 + 4 * w + j) * WW + x0 + 4 * lane) = o[j];
            } else {
                const int t = t0 + plane;
                const float *sx, *sy;
                if (p == 0) {
                    sx = xin + (size_t)t * 3 * NPIX;
                    sy = yin + (size_t)t * 3 * NPIX;
                } else {
                    sx = g_buf[rp][0] + (size_t)t * NPIX;
                    sy = g_buf[rp][1] + (size_t)t * NPIX;
                }
                float4 ox[4], oy[4];
                if (plane == 0) {
                    if (p == 0) { sconv_tile<3>(&S, sx, x0, y0, lane, w, ox);
                                  sconv_tile<3>(&S, sy, x0, y0, lane, w, oy); }
                    else        { sconv_tile<1>(&S, sx, x0, y0, lane, w, ox);
                                  sconv_tile<1>(&S, sy, x0, y0, lane, w, oy); }
                } else {
                    if (p == 0) { dconv_tile<3>(&S, sx, x0, y0, lane, w, xlo, xhi, ox);
                                  dconv_tile<3>(&S, sy, x0, y0, lane, w, xlo, xhi, oy); }
                    else        { dconv_tile<1>(&S, sx, x0, y0, lane, w, xlo, xhi, ox);
                                  dconv_tile<1>(&S, sy, x0, y0, lane, w, xlo, xhi, oy); }
                }
                float su = 0, su2 = 0, sv = 0, sv2 = 0, suv = 0;
#pragma unroll
                for (int j = 0; j < 4; j++) mom_acc(ox[j], oy[j], su, su2, sv, sv2, suv);
                mom_emit(&S, su, su2, sv, sv2, suv, lane, w, tid, t, tile);
            }
        }
        gbar(nblocks, (unsigned)(p + 1), tid);
    }

    if (blockIdx.x == 0) {
        finalize_dev(out, tid);
        if (tid == 0) {
            g_taskctr[0] = 0; g_taskctr[1] = 0;
            g_taskctr[2] = 0; g_taskctr[3] = 0;
            __threadfence();
            g_sense = 0;   // reset for next graph replay
        }
    }
}

// ---------------------------------------------------------------------------
extern "C" void kernel_launch(void* const* d_in, const int* in_sizes, int n_in,
                              void* d_out, int out_size) {
    const float* x = (const float*)d_in[0];
    const float* y = (const float*)d_in[1];
    float* out = (float*)d_out;

    int dev = 0;
    cudaGetDevice(&dev);
    int sms = 148;
    cudaDeviceGetAttribute(&sms, cudaDevAttrMultiProcessorCount, dev);
    int occ = 1;
    cudaOccupancyMaxActiveBlocksPerMultiprocessor(&occ, ssim_persist, 256, 0);
    if (occ < 1) occ = 1;
    int nblocks = sms * occ;

    ssim_persist<<<nblocks, 256>>>(x, y, out, nblocks);
}

// round 12
// speedup vs baseline: 1.3576x; 1.0283x over previous
#include <cuda_runtime.h>

#define HH 1024
#define WW 1024
#define NPIX (HH * WW)
#define NB 8
#define NBLK 256    // stats tiles per plane: 8 x 32 (128x32)
#define NCONVT 128  // conv tiles per plane: 8 x 16 (128x64)

#define P_ 0.19487471f   // sqrt(0.03797616)
#define Q_ 0.23021729f   // sqrt(0.053); outer([p,q,p],[p,q,p]) == reference 3x3
#define WFULL 0xffffffffu

__device__ float    g_buf[2][2][NB * NPIX];
__device__ float    g_part[NB][5][NBLK];
__device__ unsigned g_barcnt;
__device__ volatile unsigned g_sense;
__device__ unsigned g_taskctr[4];

struct TileC {                      // conv tasks: 128x64 out, halo-2
    float h1[68][128];
    float elo[68], ehi[68];
};
struct TileS {                      // stats tasks: 128x32 out
    float h1[36][128];
    float elo[36], ehi[36];
    float red[5][8];
};
#define SMEM_BYTES (sizeof(TileC) > sizeof(TileS) ? sizeof(TileC) : sizeof(TileS))

__inline__ __device__ float warpSumF(float v) {
#pragma unroll
    for (int o = 16; o; o >>= 1) v += __shfl_down_sync(WFULL, v, o);
    return v;
}
__inline__ __device__ double warpSumD(double v) {
#pragma unroll
    for (int o = 16; o; o >>= 1) v += __shfl_down_sync(WFULL, v, o);
    return v;
}

__device__ __forceinline__ float4 vpass(float4 a, float4 b, float4 c) {
    return make_float4(P_ * (a.x + c.x) + Q_ * b.x,
                       P_ * (a.y + c.y) + Q_ * b.y,
                       P_ * (a.z + c.z) + Q_ * b.z,
                       P_ * (a.w + c.w) + Q_ * b.w);
}

// ---- row load: thread's float4 of row gy + edge scalars for lanes 0/31 ----
template <int NCH>
__device__ __forceinline__ float4 load_row(const float* __restrict__ s, int gy,
                                           int x0, int lane, float& e0, float& e1) {
    e0 = 0.f; e1 = 0.f;
    if ((unsigned)gy >= HH) return make_float4(0.f, 0.f, 0.f, 0.f);
    const float* r = s + (size_t)gy * WW;
    const float* q = r + x0 + lane * 4;
    float4 a = *(const float4*)q;
    if (NCH == 3) {
        float4 b = *(const float4*)(q + NPIX);
        float4 c = *(const float4*)(q + 2 * NPIX);
        a.x += b.x + c.x; a.y += b.y + c.y; a.z += b.z + c.z; a.w += b.w + c.w;
    }
    if (lane == 0) {
        if (x0 > 0) {
            e0 = r[x0 - 2]; e1 = r[x0 - 1];
            if (NCH == 3) {
                e0 += r[x0 - 2 + NPIX] + r[x0 - 2 + 2 * NPIX];
                e1 += r[x0 - 1 + NPIX] + r[x0 - 1 + 2 * NPIX];
            }
        }
    } else if (lane == 31) {
        if (x0 < WW - 128) {
            e0 = r[x0 + 128]; e1 = r[x0 + 129];
            if (NCH == 3) {
                e0 += r[x0 + 128 + NPIX] + r[x0 + 128 + 2 * NPIX];
                e1 += r[x0 + 129 + NPIX] + r[x0 + 129 + 2 * NPIX];
            }
        }
    }
    return a;
}

// ---- horizontal conv of a register row via shuffles ----------------------
__device__ __forceinline__ float4 hshuf(float4 x, float e0, float e1, int lane) {
    float xl = __shfl_up_sync(WFULL, x.w, 1);   if (lane == 0)  xl = e1;
    float xr = __shfl_down_sync(WFULL, x.x, 1); if (lane == 31) xr = e0;
    return make_float4(P_ * (xl + x.y) + Q_ * x.x,
                       P_ * (x.x + x.z) + Q_ * x.y,
                       P_ * (x.y + x.w) + Q_ * x.z,
                       P_ * (x.z + xr) + Q_ * x.w);
}

// ===========================================================================
// CONV tasks: 128x64 tiles, rolling-window double conv
// ===========================================================================

// h2 row rv (gv = y0-1+rv) from h1 rows rv..rv+2 already in a0,a1,a2.
__device__ __forceinline__ float4 h2row(TileC* S, float4 a0, float4 a1, float4 a2,
                                        int rv, int y0, int lane, bool xlo, bool xhi) {
    float4 v = vpass(a0, a1, a2);
    float ve = 0.f;
    if (lane == 0)
        ve = P_ * (S->elo[rv] + S->elo[rv + 2]) + Q_ * S->elo[rv + 1];
    else if (lane == 31)
        ve = P_ * (S->ehi[rv] + S->ehi[rv + 2]) + Q_ * S->ehi[rv + 1];
    int gv = y0 - 1 + rv;
    if ((unsigned)gv >= HH) { v = make_float4(0.f, 0.f, 0.f, 0.f); ve = 0.f; }
    if (lane == 0 && xlo)  ve = 0.f;   // col -1 outside image
    if (lane == 31 && xhi) ve = 0.f;   // col 1024 outside image
    float vl = __shfl_up_sync(WFULL, v.w, 1);   if (lane == 0)  vl = ve;
    float vr = __shfl_down_sync(WFULL, v.x, 1); if (lane == 31) vr = ve;
    float4 g;
    g.x = P_ * (vl + v.y) + Q_ * v.x;
    g.y = P_ * (v.x + v.z) + Q_ * v.y;
    g.z = P_ * (v.y + v.w) + Q_ * v.z;
    g.w = P_ * (v.z + vr) + Q_ * v.w;
    return g;
}

// Full conv task (NO leading sync: caller's task-fetch sync protects smem).
template <int NCH>
__device__ void conv_task64(TileC* S, const float* __restrict__ src,
                            float* __restrict__ dst, int x0, int y0,
                            int lane, int w, bool xlo, bool xhi) {
    // h1 load: 68 rows (gy = y0-2+r)
#pragma unroll
    for (int k = 0; k < 9; k++) {
        int r = w + 8 * k;
        if (r < 68) {
            float e0, e1;
            float4 x = load_row<NCH>(src, y0 - 2 + r, x0, lane, e0, e1);
            float4 h = hshuf(x, e0, e1, lane);
            *(float4*)&S->h1[r][4 * lane] = h;
            if (lane == 0)  S->elo[r] = P_ * (e0 + x.x) + Q_ * e1;  // col -1
            if (lane == 31) S->ehi[r] = P_ * (x.w + e1) + Q_ * e0;  // col 128
        }
    }
    __syncthreads();
    // rolling-window epilogue: warp w outputs rows y0+8w .. y0+8w+7
    const int base = 8 * w;
    float4 a0 = *(float4*)&S->h1[base][4 * lane];
    float4 a1 = *(float4*)&S->h1[base + 1][4 * lane];
    float4 a2 = *(float4*)&S->h1[base + 2][4 * lane];
    float4 g0 = h2row(S, a0, a1, a2, base, y0, lane, xlo, xhi);
    a0 = a1; a1 = a2;
    a2 = *(float4*)&S->h1[base + 3][4 * lane];
    float4 g1 = h2row(S, a0, a1, a2, base + 1, y0, lane, xlo, xhi);
    a0 = a1; a1 = a2;
#pragma unroll
    for (int j = 0; j < 8; j++) {
        a2 = *(float4*)&S->h1[base + j + 4][4 * lane];
        float4 g2 = h2row(S, a0, a1, a2, base + j + 2, y0, lane, xlo, xhi);
        float4 o = vpass(g0, g1, g2);
        *(float4*)(dst + (size_t)(y0 + base + j) * WW + x0 + 4 * lane) = o;
        g0 = g1; g1 = g2; a0 = a1; a1 = a2;
    }
}

// ===========================================================================
// STATS tasks: 128x32 tiles (proven R10 path)
// ===========================================================================

template <int NCH>
__device__ __forceinline__ void h1_double(TileS* S, const float* __restrict__ src,
                                          int x0, int y0, int lane, int w) {
#pragma unroll
    for (int k = 0; k < 5; k++) {
        int r = w + 8 * k;
        if (r < 36) {
            float e0, e1;
            float4 x = load_row<NCH>(src, y0 - 2 + r, x0, lane, e0, e1);
            float4 h = hshuf(x, e0, e1, lane);
            *(float4*)&S->h1[r][4 * lane] = h;
            if (lane == 0)  S->elo[r] = P_ * (e0 + x.x) + Q_ * e1;
            if (lane == 31) S->ehi[r] = P_ * (x.w + e1) + Q_ * e0;
        }
    }
}

template <int NCH>
__device__ __forceinline__ void h1_single(TileS* S, const float* __restrict__ src,
                                          int x0, int y0, int lane, int w) {
#pragma unroll
    for (int k = 0; k < 5; k++) {
        int r = w + 8 * k;
        if (r < 34) {
            float e0, e1;
            float4 x = load_row<NCH>(src, y0 - 1 + r, x0, lane, e0, e1);
            *(float4*)&S->h1[r][4 * lane] = hshuf(x, e0, e1, lane);
        }
    }
}

__device__ __forceinline__ void vfused_double(TileS* S, int y0, int lane, int w,
                                              bool xlo, bool xhi, float4 o[4]) {
    float4 g[6];
    float4 a0 = *(float4*)&S->h1[4 * w][4 * lane];
    float4 a1 = *(float4*)&S->h1[4 * w + 1][4 * lane];
#pragma unroll
    for (int m = 0; m < 6; m++) {
        const int rv = 4 * w + m;
        float4 a2 = *(float4*)&S->h1[rv + 2][4 * lane];
        float4 v = vpass(a0, a1, a2);
        float ve = 0.f;
        if (lane == 0)
            ve = P_ * (S->elo[rv] + S->elo[rv + 2]) + Q_ * S->elo[rv + 1];
        else if (lane == 31)
            ve = P_ * (S->ehi[rv] + S->ehi[rv + 2]) + Q_ * S->ehi[rv + 1];
        int gv = y0 - 1 + rv;
        if ((unsigned)gv >= HH) { v = make_float4(0.f, 0.f, 0.f, 0.f); ve = 0.f; }
        if (lane == 0 && xlo)  ve = 0.f;
        if (lane == 31 && xhi) ve = 0.f;
        float vl = __shfl_up_sync(WFULL, v.w, 1);   if (lane == 0)  vl = ve;
        float vr = __shfl_down_sync(WFULL, v.x, 1); if (lane == 31) vr = ve;
        g[m].x = P_ * (vl + v.y) + Q_ * v.x;
        g[m].y = P_ * (v.x + v.z) + Q_ * v.y;
        g[m].z = P_ * (v.y + v.w) + Q_ * v.z;
        g[m].w = P_ * (v.z + vr) + Q_ * v.w;
        a0 = a1; a1 = a2;
    }
#pragma unroll
    for (int j = 0; j < 4; j++) o[j] = vpass(g[j], g[j + 1], g[j + 2]);
}

__device__ __forceinline__ void vfused_single(TileS* S, int lane, int w, float4 o[4]) {
    float4 a0 = *(float4*)&S->h1[4 * w][4 * lane];
    float4 a1 = *(float4*)&S->h1[4 * w + 1][4 * lane];
#pragma unroll
    for (int j = 0; j < 4; j++) {
        float4 a2 = *(float4*)&S->h1[4 * w + j + 2][4 * lane];
        o[j] = vpass(a0, a1, a2);
        a0 = a1; a1 = a2;
    }
}

template <int NCH>
__device__ __forceinline__ void dconv_tile(TileS* S, const float* __restrict__ src,
                                           int x0, int y0, int lane, int w,
                                           bool xlo, bool xhi, float4 o[4]) {
    __syncthreads();
    h1_double<NCH>(S, src, x0, y0, lane, w);
    __syncthreads();
    vfused_double(S, y0, lane, w, xlo, xhi, o);
}

template <int NCH>
__device__ __forceinline__ void sconv_tile(TileS* S, const float* __restrict__ src,
                                           int x0, int y0, int lane, int w,
                                           float4 o[4]) {
    __syncthreads();
    h1_single<NCH>(S, src, x0, y0, lane, w);
    __syncthreads();
    vfused_single(S, lane, w, o);
}

__device__ __forceinline__ void mom_acc(float4 a, float4 b, float& su, float& su2,
                                        float& sv, float& sv2, float& suv) {
    su  += a.x + a.y + a.z + a.w;
    su2 += a.x * a.x + a.y * a.y + a.z * a.z + a.w * a.w;
    sv  += b.x + b.y + b.z + b.w;
    sv2 += b.x * b.x + b.y * b.y + b.z * b.z + b.w * b.w;
    suv += a.x * b.x + a.y * b.y + a.z * b.z + a.w * b.w;
}

__device__ __forceinline__ void mom_emit(TileS* S, float su, float su2, float sv,
                                         float sv2, float suv, int lane, int w,
                                         int tid, int t, int tile) {
    su = warpSumF(su); su2 = warpSumF(su2); sv = warpSumF(sv);
    sv2 = warpSumF(sv2); suv = warpSumF(suv);
    if (lane == 0) {
        S->red[0][w] = su; S->red[1][w] = su2; S->red[2][w] = sv;
        S->red[3][w] = sv2; S->red[4][w] = suv;
    }
    __syncthreads();
    if (tid < 5) {
        float r = 0.f;
#pragma unroll
        for (int q = 0; q < 8; q++) r += S->red[tid][q];
        g_part[t][tid][tile] = r;
    }
}

// ---- global software barrier ---------------------------------------------
__device__ __forceinline__ void gbar(int nblocks, unsigned phase, int tid) {
    __syncthreads();
    if (tid == 0) {
        __threadfence();
        unsigned c = atomicAdd(&g_barcnt, 1u);
        if (c == (unsigned)nblocks - 1u) {
            g_barcnt = 0;
            __threadfence();
            g_sense = phase;
        } else {
            while (g_sense < phase) __nanosleep(64);
            __threadfence();
        }
    }
    __syncthreads();
}

// ---- finalize: 8 SSIM terms in double (block 0) --------------------------
__device__ void finalize_dev(float* __restrict__ out, int tid) {
    __shared__ double smd[NB][5];
    const int w = tid >> 5, lane = tid & 31;
    for (int idx = w; idx < NB * 5; idx += 8) {
        int t = idx / 5, m = idx - 5 * t;
        double s = 0.0;
        for (int b = lane; b < NBLK; b += 32) s += (double)g_part[t][m][b];
        s = warpSumD(s);
        if (lane == 0) smd[t][m] = s;
    }
    __syncthreads();
    if (tid == 0) {
        double tot = 0.0, sc = 1.0;
        const double N = (double)NPIX;
        const double C1 = 6.5025;    // (0.01*255)^2
        const double C2 = 58.5225;   // (0.03*255)^2
        for (int t = 0; t < NB; t++) {
            double SU = smd[t][0], SU2 = smd[t][1], SV = smd[t][2],
                   SV2 = smd[t][3], SUV = smd[t][4];
            double mu = sc * SU / N;
            double mv = sc * SV / N;
            double varu = sc * sc * (SU2 - SU * SU / N) / (N - 1.0);
            double varv = sc * sc * (SV2 - SV * SV / N) / (N - 1.0);
            double cov  = sc * sc * (SUV - SU * SV / N) / (N - 1.0);
            tot += ((2.0 * mu * mv + C1) * (2.0 * cov + C2)) /
                   ((mu * mu + mv * mv + C1) * (varu * varu + varv * varv + C2));
            sc *= 3.0;   // 3^t channel-mixing gain
        }
        out[0] = (float)tot;
    }
}

// ---------------------------------------------------------------------------
// Persistent kernel: 4 pair-phases with global barriers; work-stealing.
// Phase p (t0=2p): tasks [0,512) = stats (128x32 tiles) of images t0,t0+1;
// tasks >=512 = double conv (128x64 tiles) of future images (ping-pong).
// ---------------------------------------------------------------------------
__global__ void __launch_bounds__(256, 4)
ssim_persist(const float* __restrict__ xin, const float* __restrict__ yin,
             float* __restrict__ out, int nblocks) {
    __shared__ __align__(16) char smem_raw[SMEM_BYTES];
    __shared__ unsigned s_task;
    TileC* Sc = (TileC*)smem_raw;
    TileS* Ss = (TileS*)smem_raw;
    const int tid = threadIdx.x, lane = tid & 31, w = tid >> 5;

    for (int p = 0; p < 4; p++) {
        const int t0 = 2 * p, nimg = NB - t0;
        const int rp = (p & 1) ^ 1, wp = p & 1;
        const unsigned nstats = 2u * NBLK;
        const unsigned ntasks = nstats + (unsigned)(2 * (nimg - 2)) * NCONVT;

        for (;;) {
            __syncthreads();   // protect smem from previous task's readers
            if (tid == 0) s_task = atomicAdd(&g_taskctr[p], 1u);
            __syncthreads();
            const unsigned task = s_task;
            if (task >= ntasks) break;

            if (task >= nstats) {
                // ---- conv task: 128x64 tile ----
                const unsigned ct = task - nstats;
                const int plane2 = (int)(ct >> 7), tile = (int)(ct & 127);
                const int x0 = (tile & 7) * 128;
                const int y0 = (tile >> 3) * 64;
                const bool xlo = (x0 == 0), xhi = (x0 == WW - 128);
                int xy = (plane2 >= nimg - 2) ? 1 : 0;
                int img = t0 + 2 + plane2 - xy * (nimg - 2);
                const float* src = (p == 0)
                    ? ((xy ? yin : xin) + (size_t)img * 3 * NPIX)
                    : (g_buf[rp][xy] + (size_t)img * NPIX);
                float* dst = g_buf[wp][xy] + (size_t)img * NPIX;
                if (p == 0) conv_task64<3>(Sc, src, dst, x0, y0, lane, w, xlo, xhi);
                else        conv_task64<1>(Sc, src, dst, x0, y0, lane, w, xlo, xhi);
            } else {
                // ---- stats task: 128x32 tile ----
                const int plane = (int)(task >> 8), tile = (int)(task & 255);
                const int x0 = (tile & 7) * 128;
                const int y0 = (tile >> 3) * 32;
                const bool xlo = (x0 == 0), xhi = (x0 == WW - 128);
                const int t = t0 + plane;
                const float *sx, *sy;
                if (p == 0) {
                    sx = xin + (size_t)t * 3 * NPIX;
                    sy = yin + (size_t)t * 3 * NPIX;
                } else {
                    sx = g_buf[rp][0] + (size_t)t * NPIX;
                    sy = g_buf[rp][1] + (size_t)t * NPIX;
                }
                float4 ox[4], oy[4];
                if (plane == 0) {
                    if (p == 0) { sconv_tile<3>(Ss, sx, x0, y0, lane, w, ox);
                                  sconv_tile<3>(Ss, sy, x0, y0, lane, w, oy); }
                    else        { sconv_tile<1>(Ss, sx, x0, y0, lane, w, ox);
                                  sconv_tile<1>(Ss, sy, x0, y0, lane, w, oy); }
                } else {
                    if (p == 0) { dconv_tile<3>(Ss, sx, x0, y0, lane, w, xlo, xhi, ox);
                                  dconv_tile<3>(Ss, sy, x0, y0, lane, w, xlo, xhi, oy); }
                    else        { dconv_tile<1>(Ss, sx, x0, y0, lane, w, xlo, xhi, ox);
                                  dconv_tile<1>(Ss, sy, x0, y0, lane, w, xlo, xhi, oy); }
                }
                float su = 0, su2 = 0, sv = 0, sv2 = 0, suv = 0;
#pragma unroll
                for (int j = 0; j < 4; j++) mom_acc(ox[j], oy[j], su, su2, sv, sv2, suv);
                mom_emit(Ss, su, su2, sv, sv2, suv, lane, w, tid, t, tile);
            }
        }
        gbar(nblocks, (unsigned)(p + 1), tid);
    }

    if (blockIdx.x == 0) {
        finalize_dev(out, tid);
        if (tid == 0) {
            g_taskctr[0] = 0; g_taskctr[1] = 0;
            g_taskctr[2] = 0; g_taskctr[3] = 0;
            __threadfence();
            g_sense = 0;   // reset for next graph replay
        }
    }
}

// ---------------------------------------------------------------------------
extern "C" void kernel_launch(void* const* d_in, const int* in_sizes, int n_in,
                              void* d_out, int out_size) {
    const float* x = (const float*)d_in[0];
    const float* y = (const float*)d_in[1];
    float* out = (float*)d_out;

    int dev = 0;
    cudaGetDevice(&dev);
    int sms = 148;
    cudaDeviceGetAttribute(&sms, cudaDevAttrMultiProcessorCount, dev);
    int occ = 1;
    cudaOccupancyMaxActiveBlocksPerMultiprocessor(&occ, ssim_persist, 256, 0);
    if (occ < 1) occ = 1;
    int nblocks = sms * occ;

    ssim_persist<<<nblocks, 256>>>(x, y, out, nblocks);
}

// round 13
// speedup vs baseline: 1.3811x; 1.0173x over previous
#include <cuda_runtime.h>

#define HH 1024
#define WW 1024
#define NPIX (HH * WW)
#define NB 8
#define NBLK 256    // stats tiles per plane: 8 x 32 (128x32)
#define NCONVT 128  // conv tiles per plane: 8 x 16 (128x64)

#define P_ 0.19487471f   // sqrt(0.03797616)
#define Q_ 0.23021729f   // sqrt(0.053); outer([p,q,p],[p,q,p]) == reference 3x3
#define WFULL 0xffffffffu

__device__ float    g_buf[2][2][NB * NPIX];
__device__ float    g_part[NB][5][NBLK];
__device__ unsigned g_barcnt;
__device__ volatile unsigned g_sense;
__device__ unsigned g_taskctr[4];

struct TileC {                      // conv tasks: 128x64 out, halo-2
    float h1[68][128];
    float elo[68], ehi[68];
};
struct TileS2 {                     // stats tasks: 128x32 out, x AND y tiles
    float h1x[36][128];
    float h1y[36][128];
    float elox[36], ehix[36], eloy[36], ehiy[36];
    float red[5][8];
};
#define SMEM_BYTES (sizeof(TileS2) > sizeof(TileC) ? sizeof(TileS2) : sizeof(TileC))

__inline__ __device__ float warpSumF(float v) {
#pragma unroll
    for (int o = 16; o; o >>= 1) v += __shfl_down_sync(WFULL, v, o);
    return v;
}
__inline__ __device__ double warpSumD(double v) {
#pragma unroll
    for (int o = 16; o; o >>= 1) v += __shfl_down_sync(WFULL, v, o);
    return v;
}

__device__ __forceinline__ float4 vpass(float4 a, float4 b, float4 c) {
    return make_float4(P_ * (a.x + c.x) + Q_ * b.x,
                       P_ * (a.y + c.y) + Q_ * b.y,
                       P_ * (a.z + c.z) + Q_ * b.z,
                       P_ * (a.w + c.w) + Q_ * b.w);
}

// ---- row load: thread's float4 of row gy + edge scalars for lanes 0/31 ----
template <int NCH>
__device__ __forceinline__ float4 load_row(const float* __restrict__ s, int gy,
                                           int x0, int lane, float& e0, float& e1) {
    e0 = 0.f; e1 = 0.f;
    if ((unsigned)gy >= HH) return make_float4(0.f, 0.f, 0.f, 0.f);
    const float* r = s + (size_t)gy * WW;
    const float* q = r + x0 + lane * 4;
    float4 a = *(const float4*)q;
    if (NCH == 3) {
        float4 b = *(const float4*)(q + NPIX);
        float4 c = *(const float4*)(q + 2 * NPIX);
        a.x += b.x + c.x; a.y += b.y + c.y; a.z += b.z + c.z; a.w += b.w + c.w;
    }
    if (lane == 0) {
        if (x0 > 0) {
            e0 = r[x0 - 2]; e1 = r[x0 - 1];
            if (NCH == 3) {
                e0 += r[x0 - 2 + NPIX] + r[x0 - 2 + 2 * NPIX];
                e1 += r[x0 - 1 + NPIX] + r[x0 - 1 + 2 * NPIX];
            }
        }
    } else if (lane == 31) {
        if (x0 < WW - 128) {
            e0 = r[x0 + 128]; e1 = r[x0 + 129];
            if (NCH == 3) {
                e0 += r[x0 + 128 + NPIX] + r[x0 + 128 + 2 * NPIX];
                e1 += r[x0 + 129 + NPIX] + r[x0 + 129 + 2 * NPIX];
            }
        }
    }
    return a;
}

// ---- horizontal conv of a register row via shuffles ----------------------
__device__ __forceinline__ float4 hshuf(float4 x, float e0, float e1, int lane) {
    float xl = __shfl_up_sync(WFULL, x.w, 1);   if (lane == 0)  xl = e1;
    float xr = __shfl_down_sync(WFULL, x.x, 1); if (lane == 31) xr = e0;
    return make_float4(P_ * (xl + x.y) + Q_ * x.x,
                       P_ * (x.x + x.z) + Q_ * x.y,
                       P_ * (x.y + x.w) + Q_ * x.z,
                       P_ * (x.z + xr) + Q_ * x.w);
}

// ---- generic h1 store (NR rows, halo per HALO2 flag) ----------------------
template <int NCH, int NR, bool EDGES>
__device__ __forceinline__ void h1_store(float (*h1)[128], float* elo, float* ehi,
                                         const float* __restrict__ src,
                                         int x0, int ytop, int lane, int w) {
#pragma unroll
    for (int k = 0; k < (NR + 7) / 8; k++) {
        int r = w + 8 * k;
        if (r < NR) {
            float e0, e1;
            float4 x = load_row<NCH>(src, ytop + r, x0, lane, e0, e1);
            float4 h = hshuf(x, e0, e1, lane);
            *(float4*)&h1[r][4 * lane] = h;
            if (EDGES) {
                if (lane == 0)  elo[r] = P_ * (e0 + x.x) + Q_ * e1;  // col -1
                if (lane == 31) ehi[r] = P_ * (x.w + e1) + Q_ * e0;  // col 128
            }
        }
    }
}

// ---- h2 row rv (gv = y0-1+rv) from h1 rows rv..rv+2 (already in a0..a2) ---
__device__ __forceinline__ float4 h2row(const float* elo, const float* ehi,
                                        float4 a0, float4 a1, float4 a2,
                                        int rv, int y0, int lane, bool xlo, bool xhi) {
    float4 v = vpass(a0, a1, a2);
    float ve = 0.f;
    if (lane == 0)
        ve = P_ * (elo[rv] + elo[rv + 2]) + Q_ * elo[rv + 1];
    else if (lane == 31)
        ve = P_ * (ehi[rv] + ehi[rv + 2]) + Q_ * ehi[rv + 1];
    int gv = y0 - 1 + rv;
    if ((unsigned)gv >= HH) { v = make_float4(0.f, 0.f, 0.f, 0.f); ve = 0.f; }
    if (lane == 0 && xlo)  ve = 0.f;   // col -1 outside image
    if (lane == 31 && xhi) ve = 0.f;   // col 1024 outside image
    float vl = __shfl_up_sync(WFULL, v.w, 1);   if (lane == 0)  vl = ve;
    float vr = __shfl_down_sync(WFULL, v.x, 1); if (lane == 31) vr = ve;
    float4 g;
    g.x = P_ * (vl + v.y) + Q_ * v.x;
    g.y = P_ * (v.x + v.z) + Q_ * v.y;
    g.z = P_ * (v.y + v.w) + Q_ * v.z;
    g.w = P_ * (v.z + vr) + Q_ * v.w;
    return g;
}

// ---- conv epilogue: warp w writes output rows y0+8w .. y0+8w+7 ------------
__device__ void conv_epi(TileC* S, float* __restrict__ dst, int x0, int y0,
                         int lane, int w, bool xlo, bool xhi) {
    const int base = 8 * w;
    float4 a0 = *(float4*)&S->h1[base][4 * lane];
    float4 a1 = *(float4*)&S->h1[base + 1][4 * lane];
    float4 a2 = *(float4*)&S->h1[base + 2][4 * lane];
    float4 g0 = h2row(S->elo, S->ehi, a0, a1, a2, base, y0, lane, xlo, xhi);
    a0 = a1; a1 = a2;
    a2 = *(float4*)&S->h1[base + 3][4 * lane];
    float4 g1 = h2row(S->elo, S->ehi, a0, a1, a2, base + 1, y0, lane, xlo, xhi);
    a0 = a1; a1 = a2;
#pragma unroll
    for (int j = 0; j < 8; j++) {
        a2 = *(float4*)&S->h1[base + j + 4][4 * lane];
        float4 g2 = h2row(S->elo, S->ehi, a0, a1, a2, base + j + 2, y0, lane, xlo, xhi);
        float4 o = vpass(g0, g1, g2);
        *(float4*)(dst + (size_t)(y0 + base + j) * WW + x0 + 4 * lane) = o;
        g0 = g1; g1 = g2; a0 = a1; a1 = a2;
    }
}

// ---- moments ---------------------------------------------------------------
__device__ __forceinline__ void mom_acc(float4 a, float4 b, float& su, float& su2,
                                        float& sv, float& sv2, float& suv) {
    su  += a.x + a.y + a.z + a.w;
    su2 += a.x * a.x + a.y * a.y + a.z * a.z + a.w * a.w;
    sv  += b.x + b.y + b.z + b.w;
    sv2 += b.x * b.x + b.y * b.y + b.z * b.z + b.w * b.w;
    suv += a.x * b.x + a.y * b.y + a.z * b.z + a.w * b.w;
}

// ---- stats epilogue, double conv: fused x+y rolling windows ---------------
__device__ void stats_epi_double(TileS2* S, int y0, int lane, int w,
                                 bool xlo, bool xhi, float& su, float& su2,
                                 float& sv, float& sv2, float& suv) {
    const int b = 4 * w;
    float4 ax0 = *(float4*)&S->h1x[b][4 * lane];
    float4 ax1 = *(float4*)&S->h1x[b + 1][4 * lane];
    float4 ay0 = *(float4*)&S->h1y[b][4 * lane];
    float4 ay1 = *(float4*)&S->h1y[b + 1][4 * lane];
    float4 gx0, gx1, gy0, gy1;
#pragma unroll
    for (int m = 0; m < 6; m++) {
        const int rv = b + m;
        float4 ax2 = *(float4*)&S->h1x[rv + 2][4 * lane];
        float4 gx2 = h2row(S->elox, S->ehix, ax0, ax1, ax2, rv, y0, lane, xlo, xhi);
        float4 ay2 = *(float4*)&S->h1y[rv + 2][4 * lane];
        float4 gy2 = h2row(S->eloy, S->ehiy, ay0, ay1, ay2, rv, y0, lane, xlo, xhi);
        if (m >= 2) {
            float4 ox = vpass(gx0, gx1, gx2);
            float4 oy = vpass(gy0, gy1, gy2);
            mom_acc(ox, oy, su, su2, sv, sv2, suv);
        }
        gx0 = gx1; gx1 = gx2; gy0 = gy1; gy1 = gy2;
        ax0 = ax1; ax1 = ax2; ay0 = ay1; ay1 = ay2;
    }
}

// ---- stats epilogue, single conv -------------------------------------------
__device__ void stats_epi_single(TileS2* S, int lane, int w, float& su, float& su2,
                                 float& sv, float& sv2, float& suv) {
    const int b = 4 * w;
    float4 ax0 = *(float4*)&S->h1x[b][4 * lane];
    float4 ax1 = *(float4*)&S->h1x[b + 1][4 * lane];
    float4 ay0 = *(float4*)&S->h1y[b][4 * lane];
    float4 ay1 = *(float4*)&S->h1y[b + 1][4 * lane];
#pragma unroll
    for (int j = 0; j < 4; j++) {
        float4 ax2 = *(float4*)&S->h1x[b + j + 2][4 * lane];
        float4 ay2 = *(float4*)&S->h1y[b + j + 2][4 * lane];
        float4 ox = vpass(ax0, ax1, ax2);
        float4 oy = vpass(ay0, ay1, ay2);
        mom_acc(ox, oy, su, su2, sv, sv2, suv);
        ax0 = ax1; ax1 = ax2; ay0 = ay1; ay1 = ay2;
    }
}

// ---- global software barrier ---------------------------------------------
__device__ __forceinline__ void gbar(int nblocks, unsigned phase, int tid) {
    __syncthreads();
    if (tid == 0) {
        __threadfence();
        unsigned c = atomicAdd(&g_barcnt, 1u);
        if (c == (unsigned)nblocks - 1u) {
            g_barcnt = 0;
            __threadfence();
            g_sense = phase;
        } else {
            while (g_sense < phase) __nanosleep(64);
            __threadfence();
        }
    }
    __syncthreads();
}

// ---- finalize: 8 SSIM terms in double (block 0) --------------------------
__device__ void finalize_dev(float* __restrict__ out, int tid) {
    __shared__ double smd[NB][5];
    const int w = tid >> 5, lane = tid & 31;
    for (int idx = w; idx < NB * 5; idx += 8) {
        int t = idx / 5, m = idx - 5 * t;
        double s = 0.0;
        for (int b = lane; b < NBLK; b += 32) s += (double)g_part[t][m][b];
        s = warpSumD(s);
        if (lane == 0) smd[t][m] = s;
    }
    __syncthreads();
    if (tid == 0) {
        double tot = 0.0, sc = 1.0;
        const double N = (double)NPIX;
        const double C1 = 6.5025;    // (0.01*255)^2
        const double C2 = 58.5225;   // (0.03*255)^2
        for (int t = 0; t < NB; t++) {
            double SU = smd[t][0], SU2 = smd[t][1], SV = smd[t][2],
                   SV2 = smd[t][3], SUV = smd[t][4];
            double mu = sc * SU / N;
            double mv = sc * SV / N;
            double varu = sc * sc * (SU2 - SU * SU / N) / (N - 1.0);
            double varv = sc * sc * (SV2 - SV * SV / N) / (N - 1.0);
            double cov  = sc * sc * (SUV - SU * SV / N) / (N - 1.0);
            tot += ((2.0 * mu * mv + C1) * (2.0 * cov + C2)) /
                   ((mu * mu + mv * mv + C1) * (varu * varu + varv * varv + C2));
            sc *= 3.0;   // 3^t channel-mixing gain
        }
        out[0] = (float)tot;
    }
}

// ---------------------------------------------------------------------------
// Persistent kernel: 4 pair-phases with global barriers; work-stealing with
// pipelined ticket fetch (2 syncs/task). Phase p (t0=2p): tasks [0,512) =
// stats (128x32, x&y fused); tasks >=512 = double conv (128x64, ping-pong).
// ---------------------------------------------------------------------------
__global__ void __launch_bounds__(256, 4)
ssim_persist(const float* __restrict__ xin, const float* __restrict__ yin,
             float* __restrict__ out, int nblocks) {
    __shared__ __align__(16) char smem_raw[SMEM_BYTES];
    __shared__ unsigned s_task;
    TileC*  Sc = (TileC*)smem_raw;
    TileS2* Ss = (TileS2*)smem_raw;
    const int tid = threadIdx.x, lane = tid & 31, w = tid >> 5;

    for (int p = 0; p < 4; p++) {
        const int t0 = 2 * p, nimg = NB - t0;
        const int rp = (p & 1) ^ 1, wp = p & 1;
        const unsigned nstats = 2u * NBLK;
        const unsigned ntasks = nstats + (unsigned)(2 * (nimg - 2)) * NCONVT;

        if (tid == 0) s_task = atomicAdd(&g_taskctr[p], 1u);
        __syncthreads();
        unsigned task = s_task;

        while (task < ntasks) {
            if (task >= nstats) {
                // ---- conv task: 128x64 tile ----
                const unsigned ct = task - nstats;
                const int plane2 = (int)(ct >> 7), tile = (int)(ct & 127);
                const int x0 = (tile & 7) * 128;
                const int y0 = (tile >> 3) * 64;
                const bool xlo = (x0 == 0), xhi = (x0 == WW - 128);
                int xy = (plane2 >= nimg - 2) ? 1 : 0;
                int img = t0 + 2 + plane2 - xy * (nimg - 2);
                const float* src = (p == 0)
                    ? ((xy ? yin : xin) + (size_t)img * 3 * NPIX)
                    : (g_buf[rp][xy] + (size_t)img * NPIX);
                float* dst = g_buf[wp][xy] + (size_t)img * NPIX;

                if (p == 0) h1_store<3, 68, true>(Sc->h1, Sc->elo, Sc->ehi, src, x0, y0 - 2, lane, w);
                else        h1_store<1, 68, true>(Sc->h1, Sc->elo, Sc->ehi, src, x0, y0 - 2, lane, w);
                if (tid == 0) s_task = atomicAdd(&g_taskctr[p], 1u);  // pipelined fetch
                __syncthreads();   // h1 ready + ticket published
                conv_epi(Sc, dst, x0, y0, lane, w, xlo, xhi);
                unsigned nxt = s_task;
                __syncthreads();   // epilogue done; smem free for next task
                task = nxt;
            } else {
                // ---- stats task: 128x32 tile, x & y fused ----
                const int plane = (int)(task >> 8), tile = (int)(task & 255);
                const int x0 = (tile & 7) * 128;
                const int y0 = (tile >> 3) * 32;
                const bool xlo = (x0 == 0), xhi = (x0 == WW - 128);
                const int t = t0 + plane;
                const float *sx, *sy;
                if (p == 0) {
                    sx = xin + (size_t)t * 3 * NPIX;
                    sy = yin + (size_t)t * 3 * NPIX;
                } else {
                    sx = g_buf[rp][0] + (size_t)t * NPIX;
                    sy = g_buf[rp][1] + (size_t)t * NPIX;
                }
                if (plane == 0) {
                    if (p == 0) {
                        h1_store<3, 34, false>(Ss->h1x, Ss->elox, Ss->ehix, sx, x0, y0 - 1, lane, w);
                        h1_store<3, 34, false>(Ss->h1y, Ss->eloy, Ss->ehiy, sy, x0, y0 - 1, lane, w);
                    } else {
                        h1_store<1, 34, false>(Ss->h1x, Ss->elox, Ss->ehix, sx, x0, y0 - 1, lane, w);
                        h1_store<1, 34, false>(Ss->h1y, Ss->eloy, Ss->ehiy, sy, x0, y0 - 1, lane, w);
                    }
                } else {
                    if (p == 0) {
                        h1_store<3, 36, true>(Ss->h1x, Ss->elox, Ss->ehix, sx, x0, y0 - 2, lane, w);
                        h1_store<3, 36, true>(Ss->h1y, Ss->eloy, Ss->ehiy, sy, x0, y0 - 2, lane, w);
                    } else {
                        h1_store<1, 36, true>(Ss->h1x, Ss->elox, Ss->ehix, sx, x0, y0 - 2, lane, w);
                        h1_store<1, 36, true>(Ss->h1y, Ss->eloy, Ss->ehiy, sy, x0, y0 - 2, lane, w);
                    }
                }
                if (tid == 0) s_task = atomicAdd(&g_taskctr[p], 1u);  // pipelined fetch
                __syncthreads();   // both h1 tiles ready + ticket published

                float su = 0, su2 = 0, sv = 0, sv2 = 0, suv = 0;
                if (plane == 0) stats_epi_single(Ss, lane, w, su, su2, sv, sv2, suv);
                else stats_epi_double(Ss, y0, lane, w, xlo, xhi, su, su2, sv, sv2, suv);

                su = warpSumF(su); su2 = warpSumF(su2); sv = warpSumF(sv);
                sv2 = warpSumF(sv2); suv = warpSumF(suv);
                if (lane == 0) {
                    Ss->red[0][w] = su; Ss->red[1][w] = su2; Ss->red[2][w] = sv;
                    Ss->red[3][w] = sv2; Ss->red[4][w] = suv;
                }
                unsigned nxt = s_task;
                __syncthreads();   // red ready; epilogue done; smem free next
                if (tid < 5) {
                    float r = 0.f;
#pragma unroll
                    for (int q = 0; q < 8; q++) r += Ss->red[tid][q];
                    g_part[t][tid][tile] = r;
                }
                task = nxt;
            }
        }
        gbar(nblocks, (unsigned)(p + 1), tid);
    }

    if (blockIdx.x == 0) {
        finalize_dev(out, tid);
        if (tid == 0) {
            g_taskctr[0] = 0; g_taskctr[1] = 0;
            g_taskctr[2] = 0; g_taskctr[3] = 0;
            __threadfence();
            g_sense = 0;   // reset for next graph replay
        }
    }
}

// ---------------------------------------------------------------------------
extern "C" void kernel_launch(void* const* d_in, const int* in_sizes, int n_in,
                              void* d_out, int out_size) {
    const float* x = (const float*)d_in[0];
    const float* y = (const float*)d_in[1];
    float* out = (float*)d_out;

    int dev = 0;
    cudaGetDevice(&dev);
    int sms = 148;
    cudaDeviceGetAttribute(&sms, cudaDevAttrMultiProcessorCount, dev);
    int occ = 1;
    cudaOccupancyMaxActiveBlocksPerMultiprocessor(&occ, ssim_persist, 256, 0);
    if (occ < 1) occ = 1;
    int nblocks = sms * occ;

    ssim_persist<<<nblocks, 256>>>(x, y, out, nblocks);
}

// round 15
// speedup vs baseline: 1.4365x; 1.0402x over previous
#include <cuda_runtime.h>

#define HH 1024
#define WW 1024
#define NPIX (HH * WW)
#define NB 8
#define NBLK 256    // stats tiles per plane: 8 x 32 (128x32)
#define NCONVT 128  // conv tiles per plane: 8 x 16 (128x64)

#define P_ 0.19487471f   // sqrt(0.03797616)
#define Q_ 0.23021729f   // sqrt(0.053); outer([p,q,p],[p,q,p]) == reference 3x3
#define WFULL 0xffffffffu

__device__ float    g_buf[2][2][NB * NPIX];
__device__ float    g_part[NB][5][NBLK];
__device__ unsigned g_barcnt;
__device__ volatile unsigned g_sense;
__device__ unsigned g_taskctr[4];

struct TileC {                      // conv tasks: 128x64 out, halo-2
    float h1[68][128];
    float elo[68], ehi[68];
};
struct TileS2 {                     // stats tasks: 128x32 out, x AND y tiles
    float h1x[36][128];
    float h1y[36][128];
    float elox[36], ehix[36], eloy[36], ehiy[36];
    float red[5][8];
};
#define SMEM_BYTES (sizeof(TileS2) > sizeof(TileC) ? sizeof(TileS2) : sizeof(TileC))

__inline__ __device__ float warpSumF(float v) {
#pragma unroll
    for (int o = 16; o; o >>= 1) v += __shfl_down_sync(WFULL, v, o);
    return v;
}
__inline__ __device__ double warpSumD(double v) {
#pragma unroll
    for (int o = 16; o; o >>= 1) v += __shfl_down_sync(WFULL, v, o);
    return v;
}

__device__ __forceinline__ float4 vpass(float4 a, float4 b, float4 c) {
    return make_float4(P_ * (a.x + c.x) + Q_ * b.x,
                       P_ * (a.y + c.y) + Q_ * b.y,
                       P_ * (a.z + c.z) + Q_ * b.z,
                       P_ * (a.w + c.w) + Q_ * b.w);
}

// ---- row load: thread's float4 of row gy + edge scalars for lanes 0/31 ----
// NCH==3: raw inputs (immutable during launch) -> normal cached loads.
// NCH==1: ping-pong scratch written by OTHER SMs earlier in this launch
//         across the software barrier -> MUST bypass L1 (__ldcg) or stale
//         per-SM L1 lines can be returned (weak loads don't sync).
template <int NCH>
__device__ __forceinline__ float4 load_row(const float* __restrict__ s, int gy,
                                           int x0, int lane, float& e0, float& e1) {
    e0 = 0.f; e1 = 0.f;
    if ((unsigned)gy >= HH) return make_float4(0.f, 0.f, 0.f, 0.f);
    const float* r = s + (size_t)gy * WW;
    const float* q = r + x0 + lane * 4;
    float4 a;
    if (NCH == 3) {
        a = *(const float4*)q;
        float4 b = *(const float4*)(q + NPIX);
        float4 c = *(const float4*)(q + 2 * NPIX);
        a.x += b.x + c.x; a.y += b.y + c.y; a.z += b.z + c.z; a.w += b.w + c.w;
    } else {
        a = __ldcg((const float4*)q);
    }
    if (lane == 0) {
        if (x0 > 0) {
            if (NCH == 3) {
                e0 = r[x0 - 2] + r[x0 - 2 + NPIX] + r[x0 - 2 + 2 * NPIX];
                e1 = r[x0 - 1] + r[x0 - 1 + NPIX] + r[x0 - 1 + 2 * NPIX];
            } else {
                e0 = __ldcg(r + x0 - 2);
                e1 = __ldcg(r + x0 - 1);
            }
        }
    } else if (lane == 31) {
        if (x0 < WW - 128) {
            if (NCH == 3) {
                e0 = r[x0 + 128] + r[x0 + 128 + NPIX] + r[x0 + 128 + 2 * NPIX];
                e1 = r[x0 + 129] + r[x0 + 129 + NPIX] + r[x0 + 129 + 2 * NPIX];
            } else {
                e0 = __ldcg(r + x0 + 128);
                e1 = __ldcg(r + x0 + 129);
            }
        }
    }
    return a;
}

// ---- horizontal conv of a register row via shuffles ----------------------
__device__ __forceinline__ float4 hshuf(float4 x, float e0, float e1, int lane) {
    float xl = __shfl_up_sync(WFULL, x.w, 1);   if (lane == 0)  xl = e1;
    float xr = __shfl_down_sync(WFULL, x.x, 1); if (lane == 31) xr = e0;
    return make_float4(P_ * (xl + x.y) + Q_ * x.x,
                       P_ * (x.x + x.z) + Q_ * x.y,
                       P_ * (x.y + x.w) + Q_ * x.z,
                       P_ * (x.z + xr) + Q_ * x.w);
}

// ---- generic h1 store (NR rows) -------------------------------------------
template <int NCH, int NR, bool EDGES>
__device__ __forceinline__ void h1_store(float (*h1)[128], float* elo, float* ehi,
                                         const float* __restrict__ src,
                                         int x0, int ytop, int lane, int w) {
#pragma unroll
    for (int k = 0; k < (NR + 7) / 8; k++) {
        int r = w + 8 * k;
        if (r < NR) {
            float e0, e1;
            float4 x = load_row<NCH>(src, ytop + r, x0, lane, e0, e1);
            float4 h = hshuf(x, e0, e1, lane);
            *(float4*)&h1[r][4 * lane] = h;
            if (EDGES) {
                if (lane == 0)  elo[r] = P_ * (e0 + x.x) + Q_ * e1;  // col -1
                if (lane == 31) ehi[r] = P_ * (x.w + e1) + Q_ * e0;  // col 128
            }
        }
    }
}

// ---- h2 row rv (gv = y0-1+rv) from h1 rows rv..rv+2 -----------------------
__device__ __forceinline__ float4 h2row_ld(const float (*h1)[128],
                                           const float* elo, const float* ehi,
                                           int rv, int y0, int lane,
                                           bool xlo, bool xhi) {
    float4 a0 = *(float4*)&h1[rv][4 * lane];
    float4 a1 = *(float4*)&h1[rv + 1][4 * lane];
    float4 a2 = *(float4*)&h1[rv + 2][4 * lane];
    float4 v = vpass(a0, a1, a2);
    float ve = 0.f;
    if (lane == 0)
        ve = P_ * (elo[rv] + elo[rv + 2]) + Q_ * elo[rv + 1];
    else if (lane == 31)
        ve = P_ * (ehi[rv] + ehi[rv + 2]) + Q_ * ehi[rv + 1];
    int gv = y0 - 1 + rv;
    if ((unsigned)gv >= HH) { v = make_float4(0.f, 0.f, 0.f, 0.f); ve = 0.f; }
    if (lane == 0 && xlo)  ve = 0.f;   // col -1 outside image
    if (lane == 31 && xhi) ve = 0.f;   // col 1024 outside image
    float vl = __shfl_up_sync(WFULL, v.w, 1);   if (lane == 0)  vl = ve;
    float vr = __shfl_down_sync(WFULL, v.x, 1); if (lane == 31) vr = ve;
    float4 g;
    g.x = P_ * (vl + v.y) + Q_ * v.x;
    g.y = P_ * (v.x + v.z) + Q_ * v.y;
    g.z = P_ * (v.y + v.w) + Q_ * v.z;
    g.w = P_ * (v.z + vr) + Q_ * v.w;
    return g;
}

// ---- conv epilogue: warp w writes output rows y0+8w .. y0+8w+7 ------------
__device__ void conv_epi(TileC* S, float* __restrict__ dst, int x0, int y0,
                         int lane, int w, bool xlo, bool xhi) {
    const int base = 8 * w;
    float4 g0 = h2row_ld(S->h1, S->elo, S->ehi, base, y0, lane, xlo, xhi);
    float4 g1 = h2row_ld(S->h1, S->elo, S->ehi, base + 1, y0, lane, xlo, xhi);
#pragma unroll
    for (int j = 0; j < 8; j++) {
        float4 g2 = h2row_ld(S->h1, S->elo, S->ehi, base + j + 2, y0, lane, xlo, xhi);
        float4 o = vpass(g0, g1, g2);
        *(float4*)(dst + (size_t)(y0 + base + j) * WW + x0 + 4 * lane) = o;
        g0 = g1; g1 = g2;
    }
}

// ---- moments ---------------------------------------------------------------
__device__ __forceinline__ void mom_acc(float4 a, float4 b, float& su, float& su2,
                                        float& sv, float& sv2, float& suv) {
    su  += a.x + a.y + a.z + a.w;
    su2 += a.x * a.x + a.y * a.y + a.z * a.z + a.w * a.w;
    sv  += b.x + b.y + b.z + b.w;
    sv2 += b.x * b.x + b.y * b.y + b.z * b.z + b.w * b.w;
    suv += a.x * b.x + a.y * b.y + a.z * b.z + a.w * b.w;
}

// ---- stats epilogue, double conv: low-register rolling (g windows only) ---
__device__ void stats_epi_double(TileS2* S, int y0, int lane, int w,
                                 bool xlo, bool xhi, float& su, float& su2,
                                 float& sv, float& sv2, float& suv) {
    const int b = 4 * w;
    float4 gx0, gx1, gy0, gy1;
#pragma unroll
    for (int m = 0; m < 6; m++) {
        const int rv = b + m;
        float4 gx2 = h2row_ld(S->h1x, S->elox, S->ehix, rv, y0, lane, xlo, xhi);
        float4 gy2 = h2row_ld(S->h1y, S->eloy, S->ehiy, rv, y0, lane, xlo, xhi);
        if (m >= 2) {
            float4 ox = vpass(gx0, gx1, gx2);
            float4 oy = vpass(gy0, gy1, gy2);
            mom_acc(ox, oy, su, su2, sv, sv2, suv);
        }
        gx0 = gx1; gx1 = gx2; gy0 = gy1; gy1 = gy2;
    }
}

// ---- stats epilogue, single conv -------------------------------------------
__device__ void stats_epi_single(TileS2* S, int lane, int w, float& su, float& su2,
                                 float& sv, float& sv2, float& suv) {
    const int b = 4 * w;
#pragma unroll
    for (int j = 0; j < 4; j++) {
        float4 ax0 = *(float4*)&S->h1x[b + j][4 * lane];
        float4 ax1 = *(float4*)&S->h1x[b + j + 1][4 * lane];
        float4 ax2 = *(float4*)&S->h1x[b + j + 2][4 * lane];
        float4 ox = vpass(ax0, ax1, ax2);
        float4 ay0 = *(float4*)&S->h1y[b + j][4 * lane];
        float4 ay1 = *(float4*)&S->h1y[b + j + 1][4 * lane];
        float4 ay2 = *(float4*)&S->h1y[b + j + 2][4 * lane];
        float4 oy = vpass(ay0, ay1, ay2);
        mom_acc(ox, oy, su, su2, sv, sv2, suv);
    }
}

// ---- global software barrier ---------------------------------------------
__device__ __forceinline__ void gbar(int nblocks, unsigned phase, int tid) {
    __syncthreads();
    if (tid == 0) {
        __threadfence();
        unsigned c = atomicAdd(&g_barcnt, 1u);
        if (c == (unsigned)nblocks - 1u) {
            g_barcnt = 0;
            __threadfence();
            g_sense = phase;
        } else {
            while (g_sense < phase) __nanosleep(64);
            __threadfence();
        }
    }
    __syncthreads();
}

// ---- finalize: 8 SSIM terms in double (block 0) --------------------------
__device__ void finalize_dev(float* __restrict__ out, int tid) {
    __shared__ double smd[NB][5];
    const int w = tid >> 5, lane = tid & 31;
    for (int idx = w; idx < NB * 5; idx += 8) {
        int t = idx / 5, m = idx - 5 * t;
        double s = 0.0;
        for (int b = lane; b < NBLK; b += 32)
            s += (double)__ldcg(&g_part[t][m][b]);   // cross-SM data: bypass L1
        s = warpSumD(s);
        if (lane == 0) smd[t][m] = s;
    }
    __syncthreads();
    if (tid == 0) {
        double tot = 0.0, sc = 1.0;
        const double N = (double)NPIX;
        const double C1 = 6.5025;    // (0.01*255)^2
        const double C2 = 58.5225;   // (0.03*255)^2
        for (int t = 0; t < NB; t++) {
            double SU = smd[t][0], SU2 = smd[t][1], SV = smd[t][2],
                   SV2 = smd[t][3], SUV = smd[t][4];
            double mu = sc * SU / N;
            double mv = sc * SV / N;
            double varu = sc * sc * (SU2 - SU * SU / N) / (N - 1.0);
            double varv = sc * sc * (SV2 - SV * SV / N) / (N - 1.0);
            double cov  = sc * sc * (SUV - SU * SV / N) / (N - 1.0);
            tot += ((2.0 * mu * mv + C1) * (2.0 * cov + C2)) /
                   ((mu * mu + mv * mv + C1) * (varu * varu + varv * varv + C2));
            sc *= 3.0;   // 3^t channel-mixing gain
        }
        out[0] = (float)tot;
    }
}

// ---------------------------------------------------------------------------
// Persistent kernel: 4 pair-phases with global barriers; work-stealing with
// pipelined ticket fetch. 48-reg cap -> 5 blocks/SM. Cross-barrier global
// reads use __ldcg (per-SM L1 is not coherent across the software barrier).
// ---------------------------------------------------------------------------
__global__ void __launch_bounds__(256, 5)
ssim_persist(const float* __restrict__ xin, const float* __restrict__ yin,
             float* __restrict__ out, int nblocks) {
    __shared__ __align__(16) char smem_raw[SMEM_BYTES];
    __shared__ unsigned s_task;
    TileC*  Sc = (TileC*)smem_raw;
    TileS2* Ss = (TileS2*)smem_raw;
    const int tid = threadIdx.x, lane = tid & 31, w = tid >> 5;

    for (int p = 0; p < 4; p++) {
        const int t0 = 2 * p, nimg = NB - t0;
        const int rp = (p & 1) ^ 1, wp = p & 1;
        const unsigned nstats = 2u * NBLK;
        const unsigned ntasks = nstats + (unsigned)(2 * (nimg - 2)) * NCONVT;

        if (tid == 0) s_task = atomicAdd(&g_taskctr[p], 1u);
        __syncthreads();
        unsigned task = s_task;

        while (task < ntasks) {
            if (task >= nstats) {
                // ---- conv task: 128x64 tile ----
                const unsigned ct = task - nstats;
                const int plane2 = (int)(ct >> 7), tile = (int)(ct & 127);
                const int x0 = (tile & 7) * 128;
                const int y0 = (tile >> 3) * 64;
                const bool xlo = (x0 == 0), xhi = (x0 == WW - 128);
                int xy = (plane2 >= nimg - 2) ? 1 : 0;
                int img = t0 + 2 + plane2 - xy * (nimg - 2);
                const float* src = (p == 0)
                    ? ((xy ? yin : xin) + (size_t)img * 3 * NPIX)
                    : (g_buf[rp][xy] + (size_t)img * NPIX);
                float* dst = g_buf[wp][xy] + (size_t)img * NPIX;

                if (p == 0) h1_store<3, 68, true>(Sc->h1, Sc->elo, Sc->ehi, src, x0, y0 - 2, lane, w);
                else        h1_store<1, 68, true>(Sc->h1, Sc->elo, Sc->ehi, src, x0, y0 - 2, lane, w);
                if (tid == 0) s_task = atomicAdd(&g_taskctr[p], 1u);  // pipelined fetch
                __syncthreads();   // h1 ready + ticket published
                conv_epi(Sc, dst, x0, y0, lane, w, xlo, xhi);
                unsigned nxt = s_task;
                __syncthreads();   // epilogue done; smem free for next task
                task = nxt;
            } else {
                // ---- stats task: 128x32 tile, x & y fused ----
                const int plane = (int)(task >> 8), tile = (int)(task & 255);
                const int x0 = (tile & 7) * 128;
                const int y0 = (tile >> 3) * 32;
                const bool xlo = (x0 == 0), xhi = (x0 == WW - 128);
                const int t = t0 + plane;
                const float *sx, *sy;
                if (p == 0) {
                    sx = xin + (size_t)t * 3 * NPIX;
                    sy = yin + (size_t)t * 3 * NPIX;
                } else {
                    sx = g_buf[rp][0] + (size_t)t * NPIX;
                    sy = g_buf[rp][1] + (size_t)t * NPIX;
                }
                if (plane == 0) {
                    if (p == 0) {
                        h1_store<3, 34, false>(Ss->h1x, Ss->elox, Ss->ehix, sx, x0, y0 - 1, lane, w);
                        h1_store<3, 34, false>(Ss->h1y, Ss->eloy, Ss->ehiy, sy, x0, y0 - 1, lane, w);
                    } else {
                        h1_store<1, 34, false>(Ss->h1x, Ss->elox, Ss->ehix, sx, x0, y0 - 1, lane, w);
                        h1_store<1, 34, false>(Ss->h1y, Ss->eloy, Ss->ehiy, sy, x0, y0 - 1, lane, w);
                    }
                } else {
                    if (p == 0) {
                        h1_store<3, 36, true>(Ss->h1x, Ss->elox, Ss->ehix, sx, x0, y0 - 2, lane, w);
                        h1_store<3, 36, true>(Ss->h1y, Ss->eloy, Ss->ehiy, sy, x0, y0 - 2, lane, w);
                    } else {
                        h1_store<1, 36, true>(Ss->h1x, Ss->elox, Ss->ehix, sx, x0, y0 - 2, lane, w);
                        h1_store<1, 36, true>(Ss->h1y, Ss->eloy, Ss->ehiy, sy, x0, y0 - 2, lane, w);
                    }
                }
                if (tid == 0) s_task = atomicAdd(&g_taskctr[p], 1u);  // pipelined fetch
                __syncthreads();   // both h1 tiles ready + ticket published

                float su = 0, su2 = 0, sv = 0, sv2 = 0, suv = 0;
                if (plane == 0) stats_epi_single(Ss, lane, w, su, su2, sv, sv2, suv);
                else stats_epi_double(Ss, y0, lane, w, xlo, xhi, su, su2, sv, sv2, suv);

                su = warpSumF(su); su2 = warpSumF(su2); sv = warpSumF(sv);
                sv2 = warpSumF(sv2); suv = warpSumF(suv);
                if (lane == 0) {
                    Ss->red[0][w] = su; Ss->red[1][w] = su2; Ss->red[2][w] = sv;
                    Ss->red[3][w] = sv2; Ss->red[4][w] = suv;
                }
                unsigned nxt = s_task;
                __syncthreads();   // red ready; epilogue done; smem free next
                if (tid < 5) {
                    float r = 0.f;
#pragma unroll
                    for (int q = 0; q < 8; q++) r += Ss->red[tid][q];
                    g_part[t][tid][tile] = r;
                }
                task = nxt;
            }
        }
        gbar(nblocks, (unsigned)(p + 1), tid);
    }

    if (blockIdx.x == 0) {
        finalize_dev(out, tid);
        if (tid == 0) {
            g_taskctr[0] = 0; g_taskctr[1] = 0;
            g_taskctr[2] = 0; g_taskctr[3] = 0;
            __threadfence();
            g_sense = 0;   // reset for next graph replay
        }
    }
}

// ---------------------------------------------------------------------------
extern "C" void kernel_launch(void* const* d_in, const int* in_sizes, int n_in,
                              void* d_out, int out_size) {
    const float* x = (const float*)d_in[0];
    const float* y = (const float*)d_in[1];
    float* out = (float*)d_out;

    int dev = 0;
    cudaGetDevice(&dev);
    int sms = 148;
    cudaDeviceGetAttribute(&sms, cudaDevAttrMultiProcessorCount, dev);
    int occ = 1;
    cudaOccupancyMaxActiveBlocksPerMultiprocessor(&occ, ssim_persist, 256, 0);
    if (occ < 1) occ = 1;
    int nblocks = sms * occ;

    ssim_persist<<<nblocks, 256>>>(x, y, out, nblocks);
}